// round 10
// baseline (speedup 1.0000x reference)
#include <cuda_runtime.h>
#include <cuda_bf16.h>
#include <math.h>

// ---------------- problem constants ----------------
#define Dd   128
#define DM   256
#define DI   512
#define Hh   512
#define KNN  10
#define NN   64
#define BQ   4096
#define BS   128
#define G4   2048   // 4*H

// ---------------- scratch (device globals; allocation-free) ----------------
__device__ __align__(16) float g_qnb [BQ*DM];
__device__ __align__(16) float g_snb [BS*DM];
__device__ __align__(16) float g_h1q [BQ*DI];
__device__ __align__(16) float g_ffnq[BQ*DM];
__device__ __align__(16) float g_qg  [BQ*DM];
__device__ __align__(16) float g_h1s [BS*DI];
__device__ __align__(16) float g_ffns[BS*DM];
__device__ __align__(16) float g_senc[BS*DM];
__device__ __align__(16) float g_sg  [DM];
__device__ __align__(16) float g_sgpart[G4];
__device__ __align__(16) float g_bsum [G4];
__device__ __align__(16) float g_base [BQ*G4];
__device__ __align__(16) float g_gates[BQ*G4];
__device__ __align__(16) float g_c   [BQ*Hh];
__device__ __align__(16) float g_h   [BQ*DM];
__device__ float g_sgnorm;

__device__ __forceinline__ float sigm(float x){ return 1.0f/(1.0f+expf(-x)); }

// packed fp32x2 helpers (FFMA2 path — ptxas never emits this from C++)
__device__ __forceinline__ void ffma2(unsigned long long& d,
                                      unsigned long long a, unsigned long long b){
    asm("fma.rn.f32x2 %0, %1, %2, %0;" : "+l"(d) : "l"(a), "l"(b));
}
__device__ __forceinline__ unsigned long long dup2(float b){
    unsigned long long r;
    asm("mov.b64 %0, {%1, %1};" : "=l"(r) : "f"(b));
    return r;
}
__device__ __forceinline__ float2 unpk(unsigned long long v){
    float2 f;
    asm("mov.b64 {%0, %1}, %2;" : "=f"(f.x), "=f"(f.y) : "l"(v));
    return f;
}

// ---------------- merged neighbor encoder (all 4 segments in one grid) ------
__global__ void k_neighbor_all(const int* __restrict__ query, const int* __restrict__ support,
                               const int* __restrict__ qlc, const int* __restrict__ qrc,
                               const int* __restrict__ slc, const int* __restrict__ src,
                               const float* __restrict__ emb,
                               const float* __restrict__ W, const float* __restrict__ wb,
                               const float* __restrict__ gb)
{
    __shared__ __align__(16) float cen[Dd];
    __shared__ float ents[NN][Dd];
    __shared__ float sims[NN];
    __shared__ int   sel[KNN];
    __shared__ __align__(16) float avg[DM];

    int blk = blockIdx.x;
    const int* conn; const int* pairs; int col, dstSel, sideOff, b;
    if (blk < BQ)              { b = blk;           conn = qlc; pairs = query;   col = 0; dstSel = 0; sideOff = 0;  }
    else if (blk < 2*BQ)       { b = blk - BQ;      conn = qrc; pairs = query;   col = 1; dstSel = 0; sideOff = Dd; }
    else if (blk < 2*BQ + BS)  { b = blk - 2*BQ;    conn = slc; pairs = support; col = 0; dstSel = 1; sideOff = 0;  }
    else                       { b = blk - 2*BQ-BS; conn = src; pairs = support; col = 1; dstSel = 1; sideOff = Dd; }

    int tid  = threadIdx.x;
    int lane = tid & 31;
    int w    = tid >> 5;

    int id = pairs[b*2 + col];
    if (tid < Dd) cen[tid] = emb[(size_t)id*Dd + tid];
    __syncthreads();

    // per-warp center norm
    float cs = 0.f;
    #pragma unroll
    for (int j = 0; j < 4; j++){ float v = cen[lane + 32*j]; cs += v*v; }
    #pragma unroll
    for (int off = 16; off; off >>= 1) cs += __shfl_xor_sync(0xffffffffu, cs, off);
    float cn = fmaxf(sqrtf(cs), 1e-8f);

    // 8 warps x 8 neighbors: gather ent, sim
    for (int q = 0; q < 8; q++){
        int n   = w*8 + q;
        int eid = conn[((size_t)b*NN + n)*2 + 1];
        float dot = 0.f, sq = 0.f;
        #pragma unroll
        for (int j = 0; j < 4; j++){
            float e = emb[(size_t)eid*Dd + lane + 32*j];
            ents[n][lane + 32*j] = e;
            dot += e * cen[lane + 32*j];
            sq  += e * e;
        }
        #pragma unroll
        for (int off = 16; off; off >>= 1){
            dot += __shfl_xor_sync(0xffffffffu, dot, off);
            sq  += __shfl_xor_sync(0xffffffffu, sq , off);
        }
        if (lane == 0) sims[n] = dot / (cn * fmaxf(sqrtf(sq), 1e-8f));
    }
    __syncthreads();

    // stable top-10 (lowest index wins ties -> matches jax.lax.top_k set)
    if (tid == 0){
        float local[NN];
        for (int n = 0; n < NN; n++) local[n] = sims[n];
        for (int k = 0; k < KNN; k++){
            int bi = 0; float bv = local[0];
            for (int n = 1; n < NN; n++){ if (local[n] > bv){ bv = local[n]; bi = n; } }
            sel[k] = bi; local[bi] = -1e30f;
        }
    }
    __syncthreads();

    // average selected [rel ; ent]
    if (tid < Dd){
        float se = 0.f, sr = 0.f;
        for (int k = 0; k < KNN; k++){
            int n = sel[k];
            se += ents[n][tid];
            int rid = conn[((size_t)b*NN + n)*2 + 0];
            sr += emb[(size_t)rid*Dd + tid];
        }
        avg[tid]      = sr * 0.1f;
        avg[Dd + tid] = se * 0.1f;
    }
    __syncthreads();

    // out[d] = tanh(avg . W[d,:] + wb[d] + gb[d])
    if (tid < Dd){
        float o = wb[tid] + gb[tid];
        const float4* wr = (const float4*)(W + (size_t)tid*DM);
        const float4* av = (const float4*)avg;
        #pragma unroll 8
        for (int f = 0; f < DM/4; f++){
            float4 w4 = wr[f]; float4 a4 = av[f];
            o += w4.x*a4.x + w4.y*a4.y + w4.z*a4.z + w4.w*a4.w;
        }
        float* dst = dstSel ? g_snb : g_qnb;
        dst[(size_t)b*DM + sideOff + tid] = tanhf(o);
    }
}

// ---------------- fp32x2 (FFMA2) GEMM: C[M,N] = op(A[M,K] @ W[N,K]^T + bias (+add)) ----
// BM=128, BN=128, BK=16, 256 threads, 8x8 per thread via packed f32x2 accumulators.
__global__ __launch_bounds__(256, 2) void k_gemm(int mode,
                                                 const float* __restrict__ Wext,
                                                 const float* __restrict__ biasExt)
{
    const float* A; const float* W; const float* bias; const float* add = nullptr;
    float* C; int lda, ldw, ldc, K, ldadd = 0; int relu = 0, hasAdd = 0;
    switch (mode){
      case 0: A=g_snb; lda=DM;  W=Wext; ldw=DM; bias=biasExt;  C=g_h1s;  ldc=DI; K=DM; relu=1; break;
      case 1: A=g_h1s; lda=DI;  W=Wext; ldw=DI; bias=biasExt;  C=g_ffns; ldc=DM; K=DI;          break;
      case 2: A=g_qnb; lda=DM;  W=Wext; ldw=DM; bias=biasExt;  C=g_h1q;  ldc=DI; K=DM; relu=1; break;
      case 3: A=g_h1q; lda=DI;  W=Wext; ldw=DI; bias=biasExt;  C=g_ffnq; ldc=DM; K=DI;          break;
      case 4: A=g_qg;  lda=DM;  W=Wext; ldw=DM; bias=g_bsum;   C=g_base; ldc=G4; K=DM;          break;
      default:A=g_h;   lda=DM;  W=Wext; ldw=Hh; bias=g_sgpart; C=g_gates;ldc=G4; K=DM;
              add=g_base; ldadd=G4; hasAdd=1; break;
    }

    __shared__ __align__(16) float As[16][132];
    __shared__ __align__(16) float Bs[16][132];

    int tid = threadIdx.x;
    int m0 = blockIdx.y * 128, n0 = blockIdx.x * 128;
    int tx = tid & 15, ty = tid >> 4;          // tx -> n group of 8, ty -> m group of 8
    int lm = tid >> 2, lk = (tid & 3) * 4;     // staging

    unsigned long long acc[4][8];              // [m-pair][n], each packed (m even, m odd)
    #pragma unroll
    for (int i = 0; i < 4; i++)
        #pragma unroll
        for (int j = 0; j < 8; j++) acc[i][j] = 0ull;

    for (int k0 = 0; k0 < K; k0 += 16){
        #pragma unroll
        for (int r = 0; r < 2; r++){
            int m = lm + r*64;
            float4 v = *(const float4*)&A[(size_t)(m0+m)*lda + k0 + lk];
            As[lk+0][m] = v.x; As[lk+1][m] = v.y; As[lk+2][m] = v.z; As[lk+3][m] = v.w;
            float4 u = *(const float4*)&W[(size_t)(n0+m)*ldw + k0 + lk];
            Bs[lk+0][m] = u.x; Bs[lk+1][m] = u.y; Bs[lk+2][m] = u.z; Bs[lk+3][m] = u.w;
        }
        __syncthreads();
        #pragma unroll
        for (int k = 0; k < 16; k++){
            ulonglong2 A0 = *(const ulonglong2*)&As[k][ty*8];
            ulonglong2 A1 = *(const ulonglong2*)&As[k][ty*8 + 4];
            float4 b0 = *(const float4*)&Bs[k][tx*8];
            float4 b1 = *(const float4*)&Bs[k][tx*8 + 4];
            unsigned long long Ap[4] = {A0.x, A0.y, A1.x, A1.y};
            unsigned long long bd[8] = {dup2(b0.x), dup2(b0.y), dup2(b0.z), dup2(b0.w),
                                        dup2(b1.x), dup2(b1.y), dup2(b1.z), dup2(b1.w)};
            #pragma unroll
            for (int i = 0; i < 4; i++)
                #pragma unroll
                for (int j = 0; j < 8; j++) ffma2(acc[i][j], Ap[i], bd[j]);
        }
        __syncthreads();
    }

    int n = n0 + tx*8;
    float4 bv0 = *(const float4*)&bias[n];
    float4 bv1 = *(const float4*)&bias[n + 4];
    #pragma unroll
    for (int i = 0; i < 4; i++){
        float2 u[8];
        #pragma unroll
        for (int j = 0; j < 8; j++) u[j] = unpk(acc[i][j]);
        #pragma unroll
        for (int h2 = 0; h2 < 2; h2++){
            int m = m0 + ty*8 + i*2 + h2;
            float o[8];
            #pragma unroll
            for (int j = 0; j < 8; j++) o[j] = h2 ? u[j].y : u[j].x;
            o[0]+=bv0.x; o[1]+=bv0.y; o[2]+=bv0.z; o[3]+=bv0.w;
            o[4]+=bv1.x; o[5]+=bv1.y; o[6]+=bv1.z; o[7]+=bv1.w;
            if (hasAdd){
                float4 a0 = *(const float4*)&add[(size_t)m*ldadd + n];
                float4 a1 = *(const float4*)&add[(size_t)m*ldadd + n + 4];
                o[0]+=a0.x; o[1]+=a0.y; o[2]+=a0.z; o[3]+=a0.w;
                o[4]+=a1.x; o[5]+=a1.y; o[6]+=a1.z; o[7]+=a1.w;
            }
            if (relu){
                #pragma unroll
                for (int j = 0; j < 8; j++) o[j] = fmaxf(o[j], 0.f);
            }
            *(float4*)&C[(size_t)m*ldc + n]     = make_float4(o[0],o[1],o[2],o[3]);
            *(float4*)&C[(size_t)m*ldc + n + 4] = make_float4(o[4],o[5],o[6],o[7]);
        }
    }
}

// ---------------- residual LayerNorm: y = LN(ffn + x)*g + b, one warp per row ------
__global__ void k_ln(int mode, const float* __restrict__ g, const float* __restrict__ bb, int B)
{
    int warp = (blockIdx.x * blockDim.x + threadIdx.x) >> 5;
    int lane = threadIdx.x & 31;
    if (warp >= B) return;
    const float* ffn = mode ? g_ffnq : g_ffns;
    const float* x   = mode ? g_qnb  : g_snb;
    float*       y   = mode ? g_qg   : g_senc;

    float v[8]; float s = 0.f;
    #pragma unroll
    for (int j = 0; j < 8; j++){
        size_t idx = (size_t)warp*DM + lane + 32*j;
        v[j] = ffn[idx] + x[idx];
        s += v[j];
    }
    #pragma unroll
    for (int off = 16; off; off >>= 1) s += __shfl_xor_sync(0xffffffffu, s, off);
    float mu = s * (1.0f/DM);
    float q = 0.f;
    #pragma unroll
    for (int j = 0; j < 8; j++){ float d = v[j]-mu; q += d*d; }
    #pragma unroll
    for (int off = 16; off; off >>= 1) q += __shfl_xor_sync(0xffffffffu, q, off);
    float inv = rsqrtf(q * (1.0f/DM) + 1e-5f);
    #pragma unroll
    for (int j = 0; j < 8; j++){
        int d = lane + 32*j;
        y[(size_t)warp*DM + d] = (v[j]-mu)*inv*g[d] + bb[d];
    }
}

// ---------------- support_g = mean over rows + its norm --------------------
__global__ void k_sg()
{
    int d = threadIdx.x;   // 256 threads
    float s = 0.f;
    for (int r = 0; r < BS; r++) s += g_senc[(size_t)r*DM + d];
    s *= (1.0f/BS);
    g_sg[d] = s;
    __shared__ float red[DM];
    red[d] = s*s;
    __syncthreads();
    for (int o = 128; o; o >>= 1){
        if (d < o) red[d] += red[d+o];
        __syncthreads();
    }
    if (d == 0) g_sgnorm = sqrtf(red[0]);
}

// ---------------- sg_part[j] = sg . W_hh[j, 256:512]; bsum = b_ih + b_hh --------
__global__ void k_sgpart(const float* __restrict__ Whh,
                         const float* __restrict__ bih, const float* __restrict__ bhh)
{
    __shared__ float s[DM];
    if (threadIdx.x < DM) s[threadIdx.x] = g_sg[threadIdx.x];
    __syncthreads();
    int j = blockIdx.x * blockDim.x + threadIdx.x;
    if (j >= G4) return;
    const float* w = Whh + (size_t)j*Hh + DM;
    float acc = 0.f;
    #pragma unroll 8
    for (int d = 0; d < DM; d++) acc += s[d]*w[d];
    g_sgpart[j] = acc;
    g_bsum[j]   = bih[j] + bhh[j];
}

// ---------------- LSTM cell update (float4 per thread) ---------------------
__global__ void k_cell(int step)
{
    int idx = blockIdx.x * blockDim.x + threadIdx.x;   // < BQ*Hh/4
    int b  = idx >> 7;
    int d4 = (idx & 127) * 4;
    const float* gates = (step == 0) ? g_base : g_gates;
    size_t row = (size_t)b * G4;
    float4 gi = *(const float4*)&gates[row + d4];
    float4 gf = *(const float4*)&gates[row + 512 + d4];
    float4 gg = *(const float4*)&gates[row + 1024 + d4];
    float4 go = *(const float4*)&gates[row + 1536 + d4];
    float4 cp = (step == 0) ? make_float4(0.f,0.f,0.f,0.f)
                            : *(const float4*)&g_c[(size_t)b*Hh + d4];
    float4 c;
    c.x = sigm(gf.x)*cp.x + sigm(gi.x)*tanhf(gg.x);
    c.y = sigm(gf.y)*cp.y + sigm(gi.y)*tanhf(gg.y);
    c.z = sigm(gf.z)*cp.z + sigm(gi.z)*tanhf(gg.z);
    c.w = sigm(gf.w)*cp.w + sigm(gi.w)*tanhf(gg.w);
    *(float4*)&g_c[(size_t)b*Hh + d4] = c;
    if (d4 < DM){
        float4 qg = *(const float4*)&g_qg[(size_t)b*DM + d4];
        float4 h;
        h.x = qg.x + sigm(go.x)*tanhf(c.x);
        h.y = qg.y + sigm(go.y)*tanhf(c.y);
        h.z = qg.z + sigm(go.z)*tanhf(c.z);
        h.w = qg.w + sigm(go.w)*tanhf(c.w);
        *(float4*)&g_h[(size_t)b*DM + d4] = h;
    }
}

// ---------------- final cosine vs support_g --------------------------------
__global__ void k_final(float* __restrict__ out)
{
    int warp = (blockIdx.x * blockDim.x + threadIdx.x) >> 5;
    int lane = threadIdx.x & 31;
    if (warp >= BQ) return;
    float dot = 0.f, nn = 0.f;
    #pragma unroll
    for (int j = 0; j < 8; j++){
        int d = lane + 32*j;
        float h = g_h[(size_t)warp*DM + d];
        dot += h * g_sg[d];
        nn  += h * h;
    }
    #pragma unroll
    for (int off = 16; off; off >>= 1){
        dot += __shfl_xor_sync(0xffffffffu, dot, off);
        nn  += __shfl_xor_sync(0xffffffffu, nn , off);
    }
    if (lane == 0)
        out[warp] = dot / (fmaxf(sqrtf(nn), 1e-12f) * fmaxf(g_sgnorm, 1e-12f));
}

// ---------------- launch --------------------------------------------------
extern "C" void kernel_launch(void* const* d_in, const int* in_sizes, int n_in,
                              void* d_out, int out_size)
{
    const int*   query   = (const int*)  d_in[0];
    const int*   support = (const int*)  d_in[1];
    const int*   qlc     = (const int*)  d_in[2];
    const int*   qrc     = (const int*)  d_in[4];
    const int*   slc     = (const int*)  d_in[6];
    const int*   src     = (const int*)  d_in[8];
    const float* emb     = (const float*)d_in[10];
    const float* gcnW    = (const float*)d_in[11];
    const float* gcnwb   = (const float*)d_in[12];
    const float* gcnb    = (const float*)d_in[13];
    const float* sew1    = (const float*)d_in[14];
    const float* seb1    = (const float*)d_in[15];
    const float* sew2    = (const float*)d_in[16];
    const float* seb2    = (const float*)d_in[17];
    const float* lng     = (const float*)d_in[18];
    const float* lnb     = (const float*)d_in[19];
    const float* Wih     = (const float*)d_in[20];
    const float* Whh     = (const float*)d_in[21];
    const float* bih     = (const float*)d_in[22];
    const float* bhh     = (const float*)d_in[23];
    float* out = (float*)d_out;

    // 1) all neighbor encoders in one launch (overlaps the latency-bound BS rows)
    k_neighbor_all<<<2*BQ + 2*BS, 256>>>(query, support, qlc, qrc, slc, src,
                                         emb, gcnW, gcnwb, gcnb);

    // 2) support encoder -> support_g, sg_part, bsum
    k_gemm<<<dim3(DI/128, BS/128), 256>>>(0, sew1, seb1);
    k_gemm<<<dim3(DM/128, BS/128), 256>>>(1, sew2, seb2);
    k_ln<<<BS/8, 256>>>(0, lng, lnb, BS);
    k_sg<<<1, 256>>>();
    k_sgpart<<<G4/256, 256>>>(Whh, bih, bhh);

    // 3) query encoder (support encoder on q_nb)
    k_gemm<<<dim3(DI/128, BQ/128), 256>>>(2, sew1, seb1);
    k_gemm<<<dim3(DM/128, BQ/128), 256>>>(3, sew2, seb2);
    k_ln<<<BQ/8, 256>>>(1, lng, lnb, BQ);

    // 4) base = query_g @ W_ih^T + b_ih + b_hh
    k_gemm<<<dim3(G4/128, BQ/128), 256>>>(4, Wih, nullptr);

    // 5) LSTM steps (step0: gates == base since h_r == 0)
    k_cell<<<BQ*Hh/4/256, 256>>>(0);
    for (int s = 1; s < 4; s++){
        k_gemm<<<dim3(G4/128, BQ/128), 256>>>(5, Whh, nullptr);
        k_cell<<<BQ*Hh/4/256, 256>>>(s);
    }

    // 6) cosine output
    k_final<<<BQ/8, 256>>>(out);
}

// round 11
// speedup vs baseline: 1.3110x; 1.3110x over previous
#include <cuda_runtime.h>
#include <cuda_bf16.h>
#include <math.h>

// ---------------- problem constants ----------------
#define Dd   128
#define DM   256
#define DI   512
#define Hh   512
#define KNN  10
#define NN   64
#define BQ   4096
#define BS   128
#define G4   2048   // 4*H

// ---------------- scratch (device globals; allocation-free) ----------------
__device__ __align__(16) float g_qnb [BQ*DM];
__device__ __align__(16) float g_snb [BS*DM];
__device__ __align__(16) float g_h1q [BQ*DI];
__device__ __align__(16) float g_ffnq[BQ*DM];
__device__ __align__(16) float g_qg  [BQ*DM];
__device__ __align__(16) float g_h1s [BS*DI];
__device__ __align__(16) float g_ffns[BS*DM];
__device__ __align__(16) float g_senc[BS*DM];
__device__ __align__(16) float g_sg  [DM];
__device__ __align__(16) float g_sgpart[G4];
__device__ __align__(16) float g_bsum [G4];
__device__ __align__(16) float g_base [BQ*G4];
__device__ __align__(16) float g_gates[BQ*G4];
__device__ __align__(16) float g_c   [BQ*Hh];
__device__ __align__(16) float g_h   [BQ*DM];
__device__ float g_sgnorm;

__device__ __forceinline__ float sigm(float x){ return 1.0f/(1.0f+expf(-x)); }

// ---------------- merged neighbor encoder (all 4 segments in one grid) ------
__global__ void k_neighbor_all(const int* __restrict__ query, const int* __restrict__ support,
                               const int* __restrict__ qlc, const int* __restrict__ qrc,
                               const int* __restrict__ slc, const int* __restrict__ src,
                               const float* __restrict__ emb,
                               const float* __restrict__ W, const float* __restrict__ wb,
                               const float* __restrict__ gb)
{
    __shared__ __align__(16) float cen[Dd];
    __shared__ float ents[NN][Dd];
    __shared__ float sims[NN];
    __shared__ int   sel[KNN];
    __shared__ __align__(16) float avg[DM];

    int blk = blockIdx.x;
    const int* conn; const int* pairs; int col, dstSel, sideOff, b;
    if (blk < BQ)              { b = blk;           conn = qlc; pairs = query;   col = 0; dstSel = 0; sideOff = 0;  }
    else if (blk < 2*BQ)       { b = blk - BQ;      conn = qrc; pairs = query;   col = 1; dstSel = 0; sideOff = Dd; }
    else if (blk < 2*BQ + BS)  { b = blk - 2*BQ;    conn = slc; pairs = support; col = 0; dstSel = 1; sideOff = 0;  }
    else                       { b = blk - 2*BQ-BS; conn = src; pairs = support; col = 1; dstSel = 1; sideOff = Dd; }

    int tid  = threadIdx.x;
    int lane = tid & 31;
    int w    = tid >> 5;

    int id = pairs[b*2 + col];
    if (tid < Dd) cen[tid] = emb[(size_t)id*Dd + tid];
    __syncthreads();

    // per-warp center norm
    float cs = 0.f;
    #pragma unroll
    for (int j = 0; j < 4; j++){ float v = cen[lane + 32*j]; cs += v*v; }
    #pragma unroll
    for (int off = 16; off; off >>= 1) cs += __shfl_xor_sync(0xffffffffu, cs, off);
    float cn = fmaxf(sqrtf(cs), 1e-8f);

    // 8 warps x 8 neighbors: gather ent, sim
    for (int q = 0; q < 8; q++){
        int n   = w*8 + q;
        int eid = conn[((size_t)b*NN + n)*2 + 1];
        float dot = 0.f, sq = 0.f;
        #pragma unroll
        for (int j = 0; j < 4; j++){
            float e = emb[(size_t)eid*Dd + lane + 32*j];
            ents[n][lane + 32*j] = e;
            dot += e * cen[lane + 32*j];
            sq  += e * e;
        }
        #pragma unroll
        for (int off = 16; off; off >>= 1){
            dot += __shfl_xor_sync(0xffffffffu, dot, off);
            sq  += __shfl_xor_sync(0xffffffffu, sq , off);
        }
        if (lane == 0) sims[n] = dot / (cn * fmaxf(sqrtf(sq), 1e-8f));
    }
    __syncthreads();

    // stable top-10 (lowest index wins ties -> matches jax.lax.top_k set)
    if (tid == 0){
        float local[NN];
        for (int n = 0; n < NN; n++) local[n] = sims[n];
        for (int k = 0; k < KNN; k++){
            int bi = 0; float bv = local[0];
            for (int n = 1; n < NN; n++){ if (local[n] > bv){ bv = local[n]; bi = n; } }
            sel[k] = bi; local[bi] = -1e30f;
        }
    }
    __syncthreads();

    // average selected [rel ; ent]
    if (tid < Dd){
        float se = 0.f, sr = 0.f;
        for (int k = 0; k < KNN; k++){
            int n = sel[k];
            se += ents[n][tid];
            int rid = conn[((size_t)b*NN + n)*2 + 0];
            sr += emb[(size_t)rid*Dd + tid];
        }
        avg[tid]      = sr * 0.1f;
        avg[Dd + tid] = se * 0.1f;
    }
    __syncthreads();

    // out[d] = tanh(avg . W[d,:] + wb[d] + gb[d])
    if (tid < Dd){
        float o = wb[tid] + gb[tid];
        const float4* wr = (const float4*)(W + (size_t)tid*DM);
        const float4* av = (const float4*)avg;
        #pragma unroll 8
        for (int f = 0; f < DM/4; f++){
            float4 w4 = wr[f]; float4 a4 = av[f];
            o += w4.x*a4.x + w4.y*a4.y + w4.z*a4.z + w4.w*a4.w;
        }
        float* dst = dstSel ? g_snb : g_qnb;
        dst[(size_t)b*DM + sideOff + tid] = tanhf(o);
    }
}

// ---------------- tensor-core GEMM (bf16 hi/lo 3-pass, fp32-accurate) -------
// C[M,N] = op(A[M,K] @ W[N,K]^T + bias[n] (+add)).  BM=128, BN=128, BK=32.
// 256 threads = 8 warps, warp grid 4(m) x 2(n), warp tile 32x64.
// mma.sync.aligned.m16n8k16.row.col.f32.bf16.bf16.f32.
// Split per element: hi = bf16(x), lo = bf16(x - hi); acc = hi*hi + hi*lo + lo*hi.

__device__ __forceinline__ void mma_bf16(float* d, const unsigned* a, unsigned b0, unsigned b1){
    asm volatile("mma.sync.aligned.m16n8k16.row.col.f32.bf16.bf16.f32 "
                 "{%0,%1,%2,%3}, {%4,%5,%6,%7}, {%8,%9}, {%0,%1,%2,%3};"
                 : "+f"(d[0]), "+f"(d[1]), "+f"(d[2]), "+f"(d[3])
                 : "r"(a[0]), "r"(a[1]), "r"(a[2]), "r"(a[3]), "r"(b0), "r"(b1));
}
__device__ __forceinline__ void ldsm4(unsigned* r, unsigned addr){
    asm volatile("ldmatrix.sync.aligned.m8n8.x4.shared.b16 {%0,%1,%2,%3}, [%4];"
                 : "=r"(r[0]), "=r"(r[1]), "=r"(r[2]), "=r"(r[3]) : "r"(addr));
}
__device__ __forceinline__ unsigned pack_hi(float x, float y, unsigned short& lx, unsigned short& ly){
    __nv_bfloat16 hx = __float2bfloat16(x);
    __nv_bfloat16 hy = __float2bfloat16(y);
    lx = __bfloat16_as_ushort(__float2bfloat16(x - __bfloat162float(hx)));
    ly = __bfloat16_as_ushort(__float2bfloat16(y - __bfloat162float(hy)));
    return (unsigned)__bfloat16_as_ushort(hx) | ((unsigned)__bfloat16_as_ushort(hy) << 16);
}

#define TSTRIDE 40   // bf16 elems per smem row (32 + 8 pad), 80 bytes

__global__ __launch_bounds__(256) void k_gemm(int mode,
                                              const float* __restrict__ Wext,
                                              const float* __restrict__ biasExt)
{
    const float* A; const float* W; const float* bias; const float* add = nullptr;
    float* C; int lda, ldw, ldc, K, ldadd = 0; int relu = 0, hasAdd = 0;
    switch (mode){
      case 0: A=g_snb; lda=DM;  W=Wext; ldw=DM; bias=biasExt;  C=g_h1s;  ldc=DI; K=DM; relu=1; break;
      case 1: A=g_h1s; lda=DI;  W=Wext; ldw=DI; bias=biasExt;  C=g_ffns; ldc=DM; K=DI;          break;
      case 2: A=g_qnb; lda=DM;  W=Wext; ldw=DM; bias=biasExt;  C=g_h1q;  ldc=DI; K=DM; relu=1; break;
      case 3: A=g_h1q; lda=DI;  W=Wext; ldw=DI; bias=biasExt;  C=g_ffnq; ldc=DM; K=DI;          break;
      case 4: A=g_qg;  lda=DM;  W=Wext; ldw=DM; bias=g_bsum;   C=g_base; ldc=G4; K=DM;          break;
      default:A=g_h;   lda=DM;  W=Wext; ldw=Hh; bias=g_sgpart; C=g_gates;ldc=G4; K=DM;
              add=g_base; ldadd=G4; hasAdd=1; break;
    }

    __shared__ __align__(16) unsigned short As_hi[128*TSTRIDE];
    __shared__ __align__(16) unsigned short As_lo[128*TSTRIDE];
    __shared__ __align__(16) unsigned short Bs_hi[128*TSTRIDE];
    __shared__ __align__(16) unsigned short Bs_lo[128*TSTRIDE];

    unsigned uAhi = (unsigned)__cvta_generic_to_shared(As_hi);
    unsigned uAlo = (unsigned)__cvta_generic_to_shared(As_lo);
    unsigned uBhi = (unsigned)__cvta_generic_to_shared(Bs_hi);
    unsigned uBlo = (unsigned)__cvta_generic_to_shared(Bs_lo);

    int tid  = threadIdx.x;
    int lane = tid & 31;
    int wid  = tid >> 5;
    int wm   = wid & 3;        // 4 m groups x 32 rows
    int wn   = wid >> 2;       // 2 n groups x 64 cols
    int m0   = blockIdx.y * 128, n0 = blockIdx.x * 128;

    // staging indices: each thread: one row, 16 consecutive k
    int srow = tid >> 1;
    int skk  = (tid & 1) * 16;

    float acc[2][8][4];
    #pragma unroll
    for (int mt = 0; mt < 2; mt++)
        #pragma unroll
        for (int nt = 0; nt < 8; nt++)
            #pragma unroll
            for (int j = 0; j < 4; j++) acc[mt][nt][j] = 0.f;

    // ldmatrix lane addressing (bytes)
    int aRow = wm*32 + (lane & 15);
    int aKof = (lane >> 4) << 3;
    int bRow = wn*64 + (lane & 7) + ((lane >> 4) << 3);
    int bKof = ((lane >> 3) & 1) << 3;

    for (int k0 = 0; k0 < K; k0 += 32){
        // ---- stage + split ----
        #pragma unroll
        for (int j = 0; j < 4; j++){
            int k = skk + j*4;
            float4 va = *(const float4*)&A[(size_t)(m0+srow)*lda + k0 + k];
            float4 vb = *(const float4*)&W[(size_t)(n0+srow)*ldw + k0 + k];
            unsigned short l0,l1,l2,l3;
            unsigned h01 = pack_hi(va.x, va.y, l0, l1);
            unsigned h23 = pack_hi(va.z, va.w, l2, l3);
            unsigned* aph = (unsigned*)&As_hi[srow*TSTRIDE + k];
            unsigned* apl = (unsigned*)&As_lo[srow*TSTRIDE + k];
            aph[0] = h01; aph[1] = h23;
            apl[0] = (unsigned)l0 | ((unsigned)l1 << 16);
            apl[1] = (unsigned)l2 | ((unsigned)l3 << 16);
            unsigned g01 = pack_hi(vb.x, vb.y, l0, l1);
            unsigned g23 = pack_hi(vb.z, vb.w, l2, l3);
            unsigned* bph = (unsigned*)&Bs_hi[srow*TSTRIDE + k];
            unsigned* bpl = (unsigned*)&Bs_lo[srow*TSTRIDE + k];
            bph[0] = g01; bph[1] = g23;
            bpl[0] = (unsigned)l0 | ((unsigned)l1 << 16);
            bpl[1] = (unsigned)l2 | ((unsigned)l3 << 16);
        }
        __syncthreads();

        // ---- compute: two k16 steps ----
        #pragma unroll
        for (int ks = 0; ks < 2; ks++){
            unsigned ah[2][4], al[2][4], bh[4][4], bl[4][4];
            #pragma unroll
            for (int mt = 0; mt < 2; mt++){
                unsigned off = (unsigned)(((aRow + mt*16)*TSTRIDE + ks*16 + aKof) * 2);
                ldsm4(ah[mt], uAhi + off);
                ldsm4(al[mt], uAlo + off);
            }
            #pragma unroll
            for (int bp = 0; bp < 4; bp++){
                unsigned off = (unsigned)(((bRow + bp*16)*TSTRIDE + ks*16 + bKof) * 2);
                ldsm4(bh[bp], uBhi + off);
                ldsm4(bl[bp], uBlo + off);
            }
            #pragma unroll
            for (int mt = 0; mt < 2; mt++)
                #pragma unroll
                for (int nt = 0; nt < 8; nt++){
                    unsigned b0h = bh[nt>>1][(nt&1)*2], b1h = bh[nt>>1][(nt&1)*2+1];
                    unsigned b0l = bl[nt>>1][(nt&1)*2], b1l = bl[nt>>1][(nt&1)*2+1];
                    mma_bf16(acc[mt][nt], ah[mt], b0h, b1h);
                    mma_bf16(acc[mt][nt], ah[mt], b0l, b1l);
                    mma_bf16(acc[mt][nt], al[mt], b0h, b1h);
                }
        }
        __syncthreads();
    }

    // ---- epilogue ----
    int g = lane >> 2, tig = lane & 3;
    #pragma unroll
    for (int mt = 0; mt < 2; mt++){
        #pragma unroll
        for (int nt = 0; nt < 8; nt++){
            int n = n0 + wn*64 + nt*8 + tig*2;
            float2 bv = *(const float2*)&bias[n];
            int m = m0 + wm*32 + mt*16 + g;
            float o0 = acc[mt][nt][0] + bv.x;
            float o1 = acc[mt][nt][1] + bv.y;
            float o2 = acc[mt][nt][2] + bv.x;
            float o3 = acc[mt][nt][3] + bv.y;
            if (hasAdd){
                float2 a0 = *(const float2*)&add[(size_t)m*ldadd + n];
                float2 a1 = *(const float2*)&add[(size_t)(m+8)*ldadd + n];
                o0 += a0.x; o1 += a0.y; o2 += a1.x; o3 += a1.y;
            }
            if (relu){
                o0 = fmaxf(o0,0.f); o1 = fmaxf(o1,0.f);
                o2 = fmaxf(o2,0.f); o3 = fmaxf(o3,0.f);
            }
            *(float2*)&C[(size_t)m*ldc + n]     = make_float2(o0,o1);
            *(float2*)&C[(size_t)(m+8)*ldc + n] = make_float2(o2,o3);
        }
    }
}

// ---------------- residual LayerNorm: y = LN(ffn + x)*g + b, one warp per row ------
__global__ void k_ln(int mode, const float* __restrict__ g, const float* __restrict__ bb, int B)
{
    int warp = (blockIdx.x * blockDim.x + threadIdx.x) >> 5;
    int lane = threadIdx.x & 31;
    if (warp >= B) return;
    const float* ffn = mode ? g_ffnq : g_ffns;
    const float* x   = mode ? g_qnb  : g_snb;
    float*       y   = mode ? g_qg   : g_senc;

    float v[8]; float s = 0.f;
    #pragma unroll
    for (int j = 0; j < 8; j++){
        size_t idx = (size_t)warp*DM + lane + 32*j;
        v[j] = ffn[idx] + x[idx];
        s += v[j];
    }
    #pragma unroll
    for (int off = 16; off; off >>= 1) s += __shfl_xor_sync(0xffffffffu, s, off);
    float mu = s * (1.0f/DM);
    float q = 0.f;
    #pragma unroll
    for (int j = 0; j < 8; j++){ float d = v[j]-mu; q += d*d; }
    #pragma unroll
    for (int off = 16; off; off >>= 1) q += __shfl_xor_sync(0xffffffffu, q, off);
    float inv = rsqrtf(q * (1.0f/DM) + 1e-5f);
    #pragma unroll
    for (int j = 0; j < 8; j++){
        int d = lane + 32*j;
        y[(size_t)warp*DM + d] = (v[j]-mu)*inv*g[d] + bb[d];
    }
}

// ---------------- support_g = mean over rows + its norm --------------------
__global__ void k_sg()
{
    int d = threadIdx.x;   // 256 threads
    float s = 0.f;
    for (int r = 0; r < BS; r++) s += g_senc[(size_t)r*DM + d];
    s *= (1.0f/BS);
    g_sg[d] = s;
    __shared__ float red[DM];
    red[d] = s*s;
    __syncthreads();
    for (int o = 128; o; o >>= 1){
        if (d < o) red[d] += red[d+o];
        __syncthreads();
    }
    if (d == 0) g_sgnorm = sqrtf(red[0]);
}

// ---------------- sg_part[j] = sg . W_hh[j, 256:512]; bsum = b_ih + b_hh --------
__global__ void k_sgpart(const float* __restrict__ Whh,
                         const float* __restrict__ bih, const float* __restrict__ bhh)
{
    __shared__ float s[DM];
    if (threadIdx.x < DM) s[threadIdx.x] = g_sg[threadIdx.x];
    __syncthreads();
    int j = blockIdx.x * blockDim.x + threadIdx.x;
    if (j >= G4) return;
    const float* w = Whh + (size_t)j*Hh + DM;
    float acc = 0.f;
    #pragma unroll 8
    for (int d = 0; d < DM; d++) acc += s[d]*w[d];
    g_sgpart[j] = acc;
    g_bsum[j]   = bih[j] + bhh[j];
}

// ---------------- LSTM cell update (float4 per thread) ---------------------
__global__ void k_cell(int step)
{
    int idx = blockIdx.x * blockDim.x + threadIdx.x;   // < BQ*Hh/4
    int b  = idx >> 7;
    int d4 = (idx & 127) * 4;
    const float* gates = (step == 0) ? g_base : g_gates;
    size_t row = (size_t)b * G4;
    float4 gi = *(const float4*)&gates[row + d4];
    float4 gf = *(const float4*)&gates[row + 512 + d4];
    float4 gg = *(const float4*)&gates[row + 1024 + d4];
    float4 go = *(const float4*)&gates[row + 1536 + d4];
    float4 cp = (step == 0) ? make_float4(0.f,0.f,0.f,0.f)
                            : *(const float4*)&g_c[(size_t)b*Hh + d4];
    float4 c;
    c.x = sigm(gf.x)*cp.x + sigm(gi.x)*tanhf(gg.x);
    c.y = sigm(gf.y)*cp.y + sigm(gi.y)*tanhf(gg.y);
    c.z = sigm(gf.z)*cp.z + sigm(gi.z)*tanhf(gg.z);
    c.w = sigm(gf.w)*cp.w + sigm(gi.w)*tanhf(gg.w);
    *(float4*)&g_c[(size_t)b*Hh + d4] = c;
    if (d4 < DM){
        float4 qg = *(const float4*)&g_qg[(size_t)b*DM + d4];
        float4 h;
        h.x = qg.x + sigm(go.x)*tanhf(c.x);
        h.y = qg.y + sigm(go.y)*tanhf(c.y);
        h.z = qg.z + sigm(go.z)*tanhf(c.z);
        h.w = qg.w + sigm(go.w)*tanhf(c.w);
        *(float4*)&g_h[(size_t)b*DM + d4] = h;
    }
}

// ---------------- final cosine vs support_g --------------------------------
__global__ void k_final(float* __restrict__ out)
{
    int warp = (blockIdx.x * blockDim.x + threadIdx.x) >> 5;
    int lane = threadIdx.x & 31;
    if (warp >= BQ) return;
    float dot = 0.f, nn = 0.f;
    #pragma unroll
    for (int j = 0; j < 8; j++){
        int d = lane + 32*j;
        float h = g_h[(size_t)warp*DM + d];
        dot += h * g_sg[d];
        nn  += h * h;
    }
    #pragma unroll
    for (int off = 16; off; off >>= 1){
        dot += __shfl_xor_sync(0xffffffffu, dot, off);
        nn  += __shfl_xor_sync(0xffffffffu, nn , off);
    }
    if (lane == 0)
        out[warp] = dot / (fmaxf(sqrtf(nn), 1e-12f) * fmaxf(g_sgnorm, 1e-12f));
}

// ---------------- launch --------------------------------------------------
extern "C" void kernel_launch(void* const* d_in, const int* in_sizes, int n_in,
                              void* d_out, int out_size)
{
    const int*   query   = (const int*)  d_in[0];
    const int*   support = (const int*)  d_in[1];
    const int*   qlc     = (const int*)  d_in[2];
    const int*   qrc     = (const int*)  d_in[4];
    const int*   slc     = (const int*)  d_in[6];
    const int*   src     = (const int*)  d_in[8];
    const float* emb     = (const float*)d_in[10];
    const float* gcnW    = (const float*)d_in[11];
    const float* gcnwb   = (const float*)d_in[12];
    const float* gcnb    = (const float*)d_in[13];
    const float* sew1    = (const float*)d_in[14];
    const float* seb1    = (const float*)d_in[15];
    const float* sew2    = (const float*)d_in[16];
    const float* seb2    = (const float*)d_in[17];
    const float* lng     = (const float*)d_in[18];
    const float* lnb     = (const float*)d_in[19];
    const float* Wih     = (const float*)d_in[20];
    const float* Whh     = (const float*)d_in[21];
    const float* bih     = (const float*)d_in[22];
    const float* bhh     = (const float*)d_in[23];
    float* out = (float*)d_out;

    // 1) all neighbor encoders in one launch
    k_neighbor_all<<<2*BQ + 2*BS, 256>>>(query, support, qlc, qrc, slc, src,
                                         emb, gcnW, gcnwb, gcnb);

    // 2) support encoder -> support_g, sg_part, bsum
    k_gemm<<<dim3(DI/128, BS/128), 256>>>(0, sew1, seb1);
    k_gemm<<<dim3(DM/128, BS/128), 256>>>(1, sew2, seb2);
    k_ln<<<BS/8, 256>>>(0, lng, lnb, BS);
    k_sg<<<1, 256>>>();
    k_sgpart<<<G4/256, 256>>>(Whh, bih, bhh);

    // 3) query encoder (support encoder on q_nb)
    k_gemm<<<dim3(DI/128, BQ/128), 256>>>(2, sew1, seb1);
    k_gemm<<<dim3(DM/128, BQ/128), 256>>>(3, sew2, seb2);
    k_ln<<<BQ/8, 256>>>(1, lng, lnb, BQ);

    // 4) base = query_g @ W_ih^T + b_ih + b_hh
    k_gemm<<<dim3(G4/128, BQ/128), 256>>>(4, Wih, nullptr);

    // 5) LSTM steps (step0: gates == base since h_r == 0)
    k_cell<<<BQ*Hh/4/256, 256>>>(0);
    for (int s = 1; s < 4; s++){
        k_gemm<<<dim3(G4/128, BQ/128), 256>>>(5, Whh, nullptr);
        k_cell<<<BQ*Hh/4/256, 256>>>(s);
    }

    // 6) cosine output
    k_final<<<BQ/8, 256>>>(out);
}

// round 12
// speedup vs baseline: 1.3897x; 1.0600x over previous
#include <cuda_runtime.h>
#include <cuda_bf16.h>
#include <math.h>

// ---------------- problem constants ----------------
#define Dd   128
#define DM   256
#define DI   512
#define Hh   512
#define KNN  10
#define NN   64
#define BQ   4096
#define BS   128
#define G4   2048   // 4*H
#define MT   (2*BQ + 2*BS)   // 8448 neighbor rows
#define MB   (BQ + BS)       // 4224 merged encoder rows

// ---------------- scratch (device globals; allocation-free) ----------------
__device__ __align__(16) float g_avg [MT*DM];
__device__ __align__(16) float g_nb  [MB*DM];
__device__ __align__(16) float g_h1  [MB*DI];
__device__ __align__(16) float g_ffn [MB*DM];
__device__ __align__(16) float g_enc [MB*DM];   // rows 0..BQ-1 = query_g, BQ.. = senc
__device__ __align__(16) float g_sg  [DM];
__device__ __align__(16) float g_sgpart[G4];    // permuted gate layout
__device__ __align__(16) float g_bsum [G4];     // permuted gate layout
__device__ __align__(16) float g_base [BQ*G4];  // permuted gate layout
__device__ __align__(16) float g_c   [BQ*Hh];
__device__ __align__(16) float g_ha  [BQ*DM];
__device__ __align__(16) float g_hb  [BQ*DM];
__device__ float g_sgnorm;

__device__ __forceinline__ float sigm(float x){ return 1.0f/(1.0f+expf(-x)); }

// ---------------- neighbor averaging (gather + topk + mean only) ------------
__global__ void k_neighbor_avg(const int* __restrict__ query, const int* __restrict__ support,
                               const int* __restrict__ qlc, const int* __restrict__ qrc,
                               const int* __restrict__ slc, const int* __restrict__ src,
                               const float* __restrict__ emb)
{
    __shared__ __align__(16) float cen[Dd];
    __shared__ float ents[NN][Dd];
    __shared__ float sims[NN];
    __shared__ int   sel[KNN];

    int blk = blockIdx.x;
    const int* conn; const int* pairs; int col, b;
    if (blk < BQ)              { b = blk;           conn = qlc; pairs = query;   col = 0; }
    else if (blk < 2*BQ)       { b = blk - BQ;      conn = qrc; pairs = query;   col = 1; }
    else if (blk < 2*BQ + BS)  { b = blk - 2*BQ;    conn = slc; pairs = support; col = 0; }
    else                       { b = blk - 2*BQ-BS; conn = src; pairs = support; col = 1; }

    int tid  = threadIdx.x;
    int lane = tid & 31;
    int w    = tid >> 5;

    int id = pairs[b*2 + col];
    if (tid < Dd) cen[tid] = emb[(size_t)id*Dd + tid];
    __syncthreads();

    float cs = 0.f;
    #pragma unroll
    for (int j = 0; j < 4; j++){ float v = cen[lane + 32*j]; cs += v*v; }
    #pragma unroll
    for (int off = 16; off; off >>= 1) cs += __shfl_xor_sync(0xffffffffu, cs, off);
    float cn = fmaxf(sqrtf(cs), 1e-8f);

    for (int q = 0; q < 8; q++){
        int n   = w*8 + q;
        int eid = conn[((size_t)b*NN + n)*2 + 1];
        float dot = 0.f, sq = 0.f;
        #pragma unroll
        for (int j = 0; j < 4; j++){
            float e = emb[(size_t)eid*Dd + lane + 32*j];
            ents[n][lane + 32*j] = e;
            dot += e * cen[lane + 32*j];
            sq  += e * e;
        }
        #pragma unroll
        for (int off = 16; off; off >>= 1){
            dot += __shfl_xor_sync(0xffffffffu, dot, off);
            sq  += __shfl_xor_sync(0xffffffffu, sq , off);
        }
        if (lane == 0) sims[n] = dot / (cn * fmaxf(sqrtf(sq), 1e-8f));
    }
    __syncthreads();

    if (tid == 0){
        float local[NN];
        for (int n = 0; n < NN; n++) local[n] = sims[n];
        for (int k = 0; k < KNN; k++){
            int bi = 0; float bv = local[0];
            for (int n = 1; n < NN; n++){ if (local[n] > bv){ bv = local[n]; bi = n; } }
            sel[k] = bi; local[bi] = -1e30f;
        }
    }
    __syncthreads();

    if (tid < Dd){
        float se = 0.f, sr = 0.f;
        for (int k = 0; k < KNN; k++){
            int n = sel[k];
            se += ents[n][tid];
            int rid = conn[((size_t)b*NN + n)*2 + 0];
            sr += emb[(size_t)rid*Dd + tid];
        }
        g_avg[(size_t)blk*DM + tid]      = sr * 0.1f;
        g_avg[(size_t)blk*DM + Dd + tid] = se * 0.1f;
    }
}

// ---------------- tensor-core GEMM (bf16 hi/lo 3-pass, fp32-accurate) -------
// BM=128, BN=128, BK=32; 8 warps (4m x 2n), warp tile 32x64.
// Epilogues: 0 = plain store(+relu), 1 = tanh + scatter into g_nb (GCN),
//            2 = fused LSTM cell (permuted gate columns, shfl exchange).

__device__ __forceinline__ void mma_bf16(float* d, const unsigned* a, unsigned b0, unsigned b1){
    asm volatile("mma.sync.aligned.m16n8k16.row.col.f32.bf16.bf16.f32 "
                 "{%0,%1,%2,%3}, {%4,%5,%6,%7}, {%8,%9}, {%0,%1,%2,%3};"
                 : "+f"(d[0]), "+f"(d[1]), "+f"(d[2]), "+f"(d[3])
                 : "r"(a[0]), "r"(a[1]), "r"(a[2]), "r"(a[3]), "r"(b0), "r"(b1));
}
__device__ __forceinline__ void ldsm4(unsigned* r, unsigned addr){
    asm volatile("ldmatrix.sync.aligned.m8n8.x4.shared.b16 {%0,%1,%2,%3}, [%4];"
                 : "=r"(r[0]), "=r"(r[1]), "=r"(r[2]), "=r"(r[3]) : "r"(addr));
}
__device__ __forceinline__ unsigned pack_hi(float x, float y, unsigned short& lx, unsigned short& ly){
    __nv_bfloat16 hx = __float2bfloat16(x);
    __nv_bfloat16 hy = __float2bfloat16(y);
    lx = __bfloat16_as_ushort(__float2bfloat16(x - __bfloat162float(hx)));
    ly = __bfloat16_as_ushort(__float2bfloat16(y - __bfloat162float(hy)));
    return (unsigned)__bfloat16_as_ushort(hx) | ((unsigned)__bfloat16_as_ushort(hy) << 16);
}

#define TSTRIDE 40   // bf16 elems per smem row (32 + 8 pad)

__global__ __launch_bounds__(256) void k_gemm(int mode, int hsel,
                                              const float* __restrict__ Wext,
                                              const float* __restrict__ biasA,
                                              const float* __restrict__ biasB)
{
    const float* A; const float* W = Wext; const float* bias = biasA; const float* add = nullptr;
    float* C = nullptr; float* hout = nullptr;
    int lda, ldw, ldc = 0, K;
    int relu = 0, hasAdd = 0, epi = 0, permW = 0, storeBase = 0, cpZero = 0;
    switch (mode){
      case 0: A=g_nb;  lda=DM; ldw=DM; C=g_h1;  ldc=DI; K=DM; relu=1; break;
      case 1: A=g_h1;  lda=DI; ldw=DI; C=g_ffn; ldc=DM; K=DI;          break;
      case 4: A=g_enc; lda=DM; ldw=DM; bias=g_bsum; K=DM;
              epi=2; permW=1; storeBase=1; cpZero=1; hout=g_ha; break;
      case 5: A = hsel ? g_hb : g_ha; hout = hsel ? g_ha : g_hb;
              lda=DM; ldw=Hh; bias=g_sgpart; add=g_base; K=DM;
              epi=2; permW=1; hasAdd=1; break;
      default:A=g_avg; lda=DM; ldw=DM; K=DM; epi=1; break;   // mode 6: GCN
    }

    __shared__ __align__(16) unsigned short As_hi[128*TSTRIDE];
    __shared__ __align__(16) unsigned short As_lo[128*TSTRIDE];
    __shared__ __align__(16) unsigned short Bs_hi[128*TSTRIDE];
    __shared__ __align__(16) unsigned short Bs_lo[128*TSTRIDE];

    unsigned uAhi = (unsigned)__cvta_generic_to_shared(As_hi);
    unsigned uAlo = (unsigned)__cvta_generic_to_shared(As_lo);
    unsigned uBhi = (unsigned)__cvta_generic_to_shared(Bs_hi);
    unsigned uBlo = (unsigned)__cvta_generic_to_shared(Bs_lo);

    int tid  = threadIdx.x;
    int lane = tid & 31;
    int wid  = tid >> 5;
    int wm   = wid & 3;
    int wn   = wid >> 2;
    int m0   = blockIdx.y * 128, n0 = blockIdx.x * 128;

    int srow = tid >> 1;
    int skk  = (tid & 1) * 16;

    int wRow = n0 + srow;
    if (permW) wRow = ((wRow & 3) << 9) | (wRow >> 2);   // p -> orig gate row

    float acc[2][8][4];
    #pragma unroll
    for (int mt = 0; mt < 2; mt++)
        #pragma unroll
        for (int nt = 0; nt < 8; nt++)
            #pragma unroll
            for (int j = 0; j < 4; j++) acc[mt][nt][j] = 0.f;

    int aRow = wm*32 + (lane & 15);
    int aKof = (lane >> 4) << 3;
    int bRow = wn*64 + (lane & 7) + ((lane >> 4) << 3);
    int bKof = ((lane >> 3) & 1) << 3;

    for (int k0 = 0; k0 < K; k0 += 32){
        #pragma unroll
        for (int j = 0; j < 4; j++){
            int k = skk + j*4;
            float4 va = *(const float4*)&A[(size_t)(m0+srow)*lda + k0 + k];
            float4 vb = *(const float4*)&W[(size_t)wRow*ldw + k0 + k];
            unsigned short l0,l1,l2,l3;
            unsigned h01 = pack_hi(va.x, va.y, l0, l1);
            unsigned h23 = pack_hi(va.z, va.w, l2, l3);
            unsigned* aph = (unsigned*)&As_hi[srow*TSTRIDE + k];
            unsigned* apl = (unsigned*)&As_lo[srow*TSTRIDE + k];
            aph[0] = h01; aph[1] = h23;
            apl[0] = (unsigned)l0 | ((unsigned)l1 << 16);
            apl[1] = (unsigned)l2 | ((unsigned)l3 << 16);
            unsigned g01 = pack_hi(vb.x, vb.y, l0, l1);
            unsigned g23 = pack_hi(vb.z, vb.w, l2, l3);
            unsigned* bph = (unsigned*)&Bs_hi[srow*TSTRIDE + k];
            unsigned* bpl = (unsigned*)&Bs_lo[srow*TSTRIDE + k];
            bph[0] = g01; bph[1] = g23;
            bpl[0] = (unsigned)l0 | ((unsigned)l1 << 16);
            bpl[1] = (unsigned)l2 | ((unsigned)l3 << 16);
        }
        __syncthreads();

        #pragma unroll
        for (int ks = 0; ks < 2; ks++){
            unsigned ah[2][4], al[2][4], bh[4][4], bl[4][4];
            #pragma unroll
            for (int mt = 0; mt < 2; mt++){
                unsigned off = (unsigned)(((aRow + mt*16)*TSTRIDE + ks*16 + aKof) * 2);
                ldsm4(ah[mt], uAhi + off);
                ldsm4(al[mt], uAlo + off);
            }
            #pragma unroll
            for (int bp = 0; bp < 4; bp++){
                unsigned off = (unsigned)(((bRow + bp*16)*TSTRIDE + ks*16 + bKof) * 2);
                ldsm4(bh[bp], uBhi + off);
                ldsm4(bl[bp], uBlo + off);
            }
            #pragma unroll
            for (int mt = 0; mt < 2; mt++)
                #pragma unroll
                for (int nt = 0; nt < 8; nt++){
                    unsigned b0h = bh[nt>>1][(nt&1)*2], b1h = bh[nt>>1][(nt&1)*2+1];
                    unsigned b0l = bl[nt>>1][(nt&1)*2], b1l = bl[nt>>1][(nt&1)*2+1];
                    mma_bf16(acc[mt][nt], ah[mt], b0h, b1h);
                    mma_bf16(acc[mt][nt], ah[mt], b0l, b1l);
                    mma_bf16(acc[mt][nt], al[mt], b0h, b1h);
                }
        }
        __syncthreads();
    }

    int grp = lane >> 2, tig = lane & 3;

    if (epi == 0){
        // plain: C = (relu?) acc + bias
        #pragma unroll
        for (int mt = 0; mt < 2; mt++){
            #pragma unroll
            for (int nt = 0; nt < 8; nt++){
                int n = n0 + wn*64 + nt*8 + tig*2;
                float2 bv = *(const float2*)&bias[n];
                int m = m0 + wm*32 + mt*16 + grp;
                float o0 = acc[mt][nt][0] + bv.x;
                float o1 = acc[mt][nt][1] + bv.y;
                float o2 = acc[mt][nt][2] + bv.x;
                float o3 = acc[mt][nt][3] + bv.y;
                if (relu){
                    o0 = fmaxf(o0,0.f); o1 = fmaxf(o1,0.f);
                    o2 = fmaxf(o2,0.f); o3 = fmaxf(o3,0.f);
                }
                *(float2*)&C[(size_t)m*ldc + n]     = make_float2(o0,o1);
                *(float2*)&C[(size_t)(m+8)*ldc + n] = make_float2(o2,o3);
            }
        }
    } else if (epi == 1){
        // GCN: tanh(acc + wb + gb), scatter into g_nb with side offset
        #pragma unroll
        for (int mt = 0; mt < 2; mt++){
            #pragma unroll
            for (int nt = 0; nt < 8; nt++){
                int n = n0 + wn*64 + nt*8 + tig*2;   // 0..127
                float wbv0 = biasA[n]   + biasB[n];
                float wbv1 = biasA[n+1] + biasB[n+1];
                #pragma unroll
                for (int h2 = 0; h2 < 2; h2++){
                    int m = m0 + wm*32 + mt*16 + grp + h2*8;
                    float o0 = tanhf(acc[mt][nt][h2*2+0] + wbv0);
                    float o1 = tanhf(acc[mt][nt][h2*2+1] + wbv1);
                    int row, off;
                    if (m < BQ)            { row = m;        off = 0;  }
                    else if (m < 2*BQ)     { row = m - BQ;   off = Dd; }
                    else if (m < 2*BQ+BS)  { row = m - BQ;   off = 0;  row = m - 2*BQ + BQ; }
                    else                   { row = m - 2*BQ - BS + BQ; off = Dd; }
                    *(float2*)&g_nb[(size_t)row*DM + off + n] = make_float2(o0,o1);
                }
            }
        }
    } else {
        // fused LSTM cell. columns are permuted: unit u occupies cols 4u..4u+3 = (i,f,g,o)
        #pragma unroll
        for (int mt = 0; mt < 2; mt++){
            #pragma unroll
            for (int nt = 0; nt < 8; nt++){
                int n = n0 + wn*64 + nt*8 + tig*2;
                int m = m0 + wm*32 + mt*16 + grp;
                float2 bv = *(const float2*)&bias[n];
                float x0 = acc[mt][nt][0] + bv.x;
                float x1 = acc[mt][nt][1] + bv.y;
                float x2 = acc[mt][nt][2] + bv.x;
                float x3 = acc[mt][nt][3] + bv.y;
                if (hasAdd){
                    float2 a0 = *(const float2*)&add[(size_t)m*G4 + n];
                    float2 a1 = *(const float2*)&add[(size_t)(m+8)*G4 + n];
                    x0 += a0.x; x1 += a0.y; x2 += a1.x; x3 += a1.y;
                }
                if (storeBase){
                    *(float2*)&g_base[(size_t)m*G4 + n]     = make_float2(x0,x1);
                    *(float2*)&g_base[(size_t)(m+8)*G4 + n] = make_float2(x2,x3);
                }
                float y0 = __shfl_xor_sync(0xffffffffu, x0, 1);
                float y1 = __shfl_xor_sync(0xffffffffu, x1, 1);
                float y2 = __shfl_xor_sync(0xffffffffu, x2, 1);
                float y3 = __shfl_xor_sync(0xffffffffu, x3, 1);
                if (!(tig & 1)){
                    // this thread holds (i,f); partner supplied (g,o)
                    int u = n >> 2;
                    float cp0 = cpZero ? 0.f : g_c[(size_t)m*Hh + u];
                    float cp1 = cpZero ? 0.f : g_c[(size_t)(m+8)*Hh + u];
                    float c0 = sigm(x1)*cp0 + sigm(x0)*tanhf(y0);
                    float c1 = sigm(x3)*cp1 + sigm(x2)*tanhf(y2);
                    g_c[(size_t)m*Hh + u]     = c0;
                    g_c[(size_t)(m+8)*Hh + u] = c1;
                    if (u < DM){
                        hout[(size_t)m*DM + u]     = g_enc[(size_t)m*DM + u]     + sigm(y1)*tanhf(c0);
                        hout[(size_t)(m+8)*DM + u] = g_enc[(size_t)(m+8)*DM + u] + sigm(y3)*tanhf(c1);
                    }
                }
            }
        }
    }
}

// ---------------- residual LayerNorm over all MB rows ----------------------
__global__ void k_ln(const float* __restrict__ g, const float* __restrict__ bb)
{
    int warp = (blockIdx.x * blockDim.x + threadIdx.x) >> 5;
    int lane = threadIdx.x & 31;
    if (warp >= MB) return;

    float v[8]; float s = 0.f;
    #pragma unroll
    for (int j = 0; j < 8; j++){
        size_t idx = (size_t)warp*DM + lane + 32*j;
        v[j] = g_ffn[idx] + g_nb[idx];
        s += v[j];
    }
    #pragma unroll
    for (int off = 16; off; off >>= 1) s += __shfl_xor_sync(0xffffffffu, s, off);
    float mu = s * (1.0f/DM);
    float q = 0.f;
    #pragma unroll
    for (int j = 0; j < 8; j++){ float d = v[j]-mu; q += d*d; }
    #pragma unroll
    for (int off = 16; off; off >>= 1) q += __shfl_xor_sync(0xffffffffu, q, off);
    float inv = rsqrtf(q * (1.0f/DM) + 1e-5f);
    #pragma unroll
    for (int j = 0; j < 8; j++){
        int d = lane + 32*j;
        g_enc[(size_t)warp*DM + d] = (v[j]-mu)*inv*g[d] + bb[d];
    }
}

// ---------------- support_g = mean of senc rows + norm ---------------------
__global__ void k_support_post()
{
    int d = threadIdx.x;   // 256
    float s = 0.f;
    for (int r = 0; r < BS; r++) s += g_enc[(size_t)(BQ + r)*DM + d];
    s *= (1.0f/BS);
    g_sg[d] = s;
    __shared__ float red[DM];
    red[d] = s*s;
    __syncthreads();
    for (int o = 128; o; o >>= 1){
        if (d < o) red[d] += red[d+o];
        __syncthreads();
    }
    if (d == 0) g_sgnorm = sqrtf(red[0]);
}

// ---------------- sgpart/bsum in PERMUTED gate layout ----------------------
__global__ void k_sgpart(const float* __restrict__ Whh,
                         const float* __restrict__ bih, const float* __restrict__ bhh)
{
    __shared__ float s[DM];
    if (threadIdx.x < DM) s[threadIdx.x] = g_sg[threadIdx.x];
    __syncthreads();
    int p = blockIdx.x * blockDim.x + threadIdx.x;
    if (p >= G4) return;
    int orig = ((p & 3) << 9) | (p >> 2);
    const float* w = Whh + (size_t)orig*Hh + DM;
    float acc = 0.f;
    #pragma unroll 8
    for (int d = 0; d < DM; d++) acc += s[d]*w[d];
    g_sgpart[p] = acc;
    g_bsum[p]   = bih[orig] + bhh[orig];
}

// ---------------- final cosine vs support_g --------------------------------
__global__ void k_final(float* __restrict__ out)
{
    int warp = (blockIdx.x * blockDim.x + threadIdx.x) >> 5;
    int lane = threadIdx.x & 31;
    if (warp >= BQ) return;
    float dot = 0.f, nn = 0.f;
    #pragma unroll
    for (int j = 0; j < 8; j++){
        int d = lane + 32*j;
        float h = g_hb[(size_t)warp*DM + d];
        dot += h * g_sg[d];
        nn  += h * h;
    }
    #pragma unroll
    for (int off = 16; off; off >>= 1){
        dot += __shfl_xor_sync(0xffffffffu, dot, off);
        nn  += __shfl_xor_sync(0xffffffffu, nn , off);
    }
    if (lane == 0)
        out[warp] = dot / (fmaxf(sqrtf(nn), 1e-12f) * fmaxf(g_sgnorm, 1e-12f));
}

// ---------------- launch --------------------------------------------------
extern "C" void kernel_launch(void* const* d_in, const int* in_sizes, int n_in,
                              void* d_out, int out_size)
{
    const int*   query   = (const int*)  d_in[0];
    const int*   support = (const int*)  d_in[1];
    const int*   qlc     = (const int*)  d_in[2];
    const int*   qrc     = (const int*)  d_in[4];
    const int*   slc     = (const int*)  d_in[6];
    const int*   src     = (const int*)  d_in[8];
    const float* emb     = (const float*)d_in[10];
    const float* gcnW    = (const float*)d_in[11];
    const float* gcnwb   = (const float*)d_in[12];
    const float* gcnb    = (const float*)d_in[13];
    const float* sew1    = (const float*)d_in[14];
    const float* seb1    = (const float*)d_in[15];
    const float* sew2    = (const float*)d_in[16];
    const float* seb2    = (const float*)d_in[17];
    const float* lng     = (const float*)d_in[18];
    const float* lnb     = (const float*)d_in[19];
    const float* Wih     = (const float*)d_in[20];
    const float* Whh     = (const float*)d_in[21];
    const float* bih     = (const float*)d_in[22];
    const float* bhh     = (const float*)d_in[23];
    float* out = (float*)d_out;

    // 1) neighbor gather + topk + average
    k_neighbor_avg<<<MT, 256>>>(query, support, qlc, qrc, slc, src, emb);

    // 2) GCN projection as GEMM with tanh+scatter epilogue -> g_nb
    k_gemm<<<dim3(1, MT/128), 256>>>(6, 0, gcnW, gcnwb, gcnb);

    // 3) merged support+query FFN + LN -> g_enc
    k_gemm<<<dim3(DI/128, MB/128), 256>>>(0, 0, sew1, seb1, nullptr);
    k_gemm<<<dim3(DM/128, MB/128), 256>>>(1, 0, sew2, seb2, nullptr);
    k_ln<<<MB/8, 256>>>(lng, lnb);

    // 4) support_g + permuted sgpart/bsum
    k_support_post<<<1, 256>>>();
    k_sgpart<<<G4/256, 256>>>(Whh, bih, bhh);

    // 5) gates GEMMs with fused cell epilogue
    k_gemm<<<dim3(G4/128, BQ/128), 256>>>(4, 0, Wih, nullptr, nullptr);   // base + step0 -> g_ha
    k_gemm<<<dim3(G4/128, BQ/128), 256>>>(5, 0, Whh, nullptr, nullptr);   // step1: ha -> hb
    k_gemm<<<dim3(G4/128, BQ/128), 256>>>(5, 1, Whh, nullptr, nullptr);   // step2: hb -> ha
    k_gemm<<<dim3(G4/128, BQ/128), 256>>>(5, 0, Whh, nullptr, nullptr);   // step3: ha -> hb

    // 6) cosine output
    k_final<<<BQ/8, 256>>>(out);
}

// round 16
// speedup vs baseline: 1.8692x; 1.3451x over previous
#include <cuda_runtime.h>
#include <cuda_bf16.h>
#include <math.h>

// ---------------- problem constants ----------------
#define Dd   128
#define DM   256
#define DI   512
#define Hh   512
#define KNN  10
#define NN   64
#define BQ   4096
#define BS   128
#define G4   2048   // 4*H
#define MT   (2*BQ + 2*BS)   // 8448 neighbor rows
#define MB   (BQ + BS)       // 4224 merged encoder rows

// ---------------- scratch (device globals; allocation-free) ----------------
__device__ __align__(16) __nv_bfloat16 g_avgh[MT*DM], g_avgl[MT*DM];
__device__ __align__(16) float         g_nb  [MB*DM];
__device__ __align__(16) __nv_bfloat16 g_nbh [MB*DM], g_nbl [MB*DM];
__device__ __align__(16) __nv_bfloat16 g_h1h [MB*DI], g_h1l [MB*DI];
__device__ __align__(16) float         g_ffn [MB*DM];
__device__ __align__(16) float         g_enc [MB*DM];
__device__ __align__(16) __nv_bfloat16 g_ench[MB*DM], g_encl[MB*DM];
__device__ __align__(16) float         g_sg  [DM];
__device__ __align__(16) float         g_sgpart[G4];   // permuted gate layout
__device__ __align__(16) float         g_bsum [G4];    // permuted gate layout
__device__ __align__(16) float         g_base [BQ*G4]; // permuted gate layout
__device__ __align__(16) float         g_c   [BQ*Hh];
__device__ __align__(16) __nv_bfloat16 g_hah[BQ*DM], g_hal[BQ*DM];
__device__ __align__(16) __nv_bfloat16 g_hbh[BQ*DM], g_hbl[BQ*DM];
__device__ __align__(16) float         g_hf [BQ*DM];
__device__ float g_sgnorm;

// split weights (bf16 hi/lo, gate rows pre-permuted)
__device__ __align__(16) __nv_bfloat16 w_gcnh[Dd*DM],  w_gcnl[Dd*DM];
__device__ __align__(16) __nv_bfloat16 w_se1h[DI*DM],  w_se1l[DI*DM];
__device__ __align__(16) __nv_bfloat16 w_se2h[DM*DI],  w_se2l[DM*DI];
__device__ __align__(16) __nv_bfloat16 w_ihh [G4*DM],  w_ihl [G4*DM];
__device__ __align__(16) __nv_bfloat16 w_hhh [G4*DM],  w_hhl [G4*DM];

__device__ __forceinline__ float sigm(float x){ return 1.0f/(1.0f+expf(-x)); }

__device__ __forceinline__ void store_hl2(__nv_bfloat16* dh, __nv_bfloat16* dl,
                                          size_t idx, float x, float y){
    __nv_bfloat16 hx = __float2bfloat16(x), hy = __float2bfloat16(y);
    __nv_bfloat162 hv; hv.x = hx; hv.y = hy;
    *(__nv_bfloat162*)&dh[idx] = hv;
    __nv_bfloat162 lv;
    lv.x = __float2bfloat16(x - __bfloat162float(hx));
    lv.y = __float2bfloat16(y - __bfloat162float(hy));
    *(__nv_bfloat162*)&dl[idx] = lv;
}
__device__ __forceinline__ void store_hl1(__nv_bfloat16* dh, __nv_bfloat16* dl,
                                          size_t idx, float x){
    __nv_bfloat16 hx = __float2bfloat16(x);
    dh[idx] = hx;
    dl[idx] = __float2bfloat16(x - __bfloat162float(hx));
}

// ---------------- weight split (fp32 -> bf16 hi/lo) ------------------------
// Destinations are __device__ globals resolved INSIDE the kernel (passing
// their addresses from host code was the R13-R15 kill-switch).
__global__ void k_splitw(int which, const float* __restrict__ src)
{
    __nv_bfloat16 *dh, *dl; int K, srcLd, perm;
    switch (which){
      case 0:  dh=w_gcnh; dl=w_gcnl; K=DM; srcLd=DM; perm=0; break;
      case 1:  dh=w_se1h; dl=w_se1l; K=DM; srcLd=DM; perm=0; break;
      case 2:  dh=w_se2h; dl=w_se2l; K=DI; srcLd=DI; perm=0; break;
      case 3:  dh=w_ihh;  dl=w_ihl;  K=DM; srcLd=DM; perm=1; break;
      default: dh=w_hhh;  dl=w_hhl;  K=DM; srcLd=Hh; perm=1; break;
    }
    int r    = blockIdx.x * 8 + (threadIdx.x >> 5);
    int lane = threadIdx.x & 31;
    int orig = perm ? (((r & 3) << 9) | (r >> 2)) : r;
    const float* s = src + (size_t)orig * srcLd;
    for (int k = lane; k < K; k += 32)
        store_hl1(dh, dl, (size_t)r*K + k, s[k]);
}

// ---------------- neighbor averaging (low-smem: re-gather selected rows) ----
__global__ void k_neighbor_avg(const int* __restrict__ query, const int* __restrict__ support,
                               const int* __restrict__ qlc, const int* __restrict__ qrc,
                               const int* __restrict__ slc, const int* __restrict__ src,
                               const float* __restrict__ emb)
{
    __shared__ __align__(16) float cen[Dd];
    __shared__ float sims[NN];
    __shared__ int   selE[KNN], selR[KNN];

    int blk = blockIdx.x;
    const int* conn; const int* pairs; int col, b;
    if (blk < BQ)              { b = blk;           conn = qlc; pairs = query;   col = 0; }
    else if (blk < 2*BQ)       { b = blk - BQ;      conn = qrc; pairs = query;   col = 1; }
    else if (blk < 2*BQ + BS)  { b = blk - 2*BQ;    conn = slc; pairs = support; col = 0; }
    else                       { b = blk - 2*BQ-BS; conn = src; pairs = support; col = 1; }

    int tid  = threadIdx.x;
    int lane = tid & 31;
    int w    = tid >> 5;

    int id = pairs[b*2 + col];
    if (tid < Dd) cen[tid] = emb[(size_t)id*Dd + tid];
    __syncthreads();

    float cs = 0.f;
    #pragma unroll
    for (int j = 0; j < 4; j++){ float v = cen[lane + 32*j]; cs += v*v; }
    #pragma unroll
    for (int off = 16; off; off >>= 1) cs += __shfl_xor_sync(0xffffffffu, cs, off);
    float cn = fmaxf(sqrtf(cs), 1e-8f);

    // 8 warps x 8 neighbors: streaming dot/norm (no ent caching)
    for (int q = 0; q < 8; q++){
        int n   = w*8 + q;
        int eid = conn[((size_t)b*NN + n)*2 + 1];
        float dot = 0.f, sq = 0.f;
        #pragma unroll
        for (int j = 0; j < 4; j++){
            float e = emb[(size_t)eid*Dd + lane + 32*j];
            dot += e * cen[lane + 32*j];
            sq  += e * e;
        }
        #pragma unroll
        for (int off = 16; off; off >>= 1){
            dot += __shfl_xor_sync(0xffffffffu, dot, off);
            sq  += __shfl_xor_sync(0xffffffffu, sq , off);
        }
        if (lane == 0) sims[n] = dot / (cn * fmaxf(sqrtf(sq), 1e-8f));
    }
    __syncthreads();

    // stable top-10 (lowest index wins ties)
    if (tid == 0){
        float local[NN];
        for (int n = 0; n < NN; n++) local[n] = sims[n];
        for (int k = 0; k < KNN; k++){
            int bi = 0; float bv = local[0];
            for (int n = 1; n < NN; n++){ if (local[n] > bv){ bv = local[n]; bi = n; } }
            local[bi] = -1e30f;
            selE[k] = conn[((size_t)b*NN + bi)*2 + 1];
            selR[k] = conn[((size_t)b*NN + bi)*2 + 0];
        }
    }
    __syncthreads();

    if (tid < Dd){
        float se = 0.f, sr = 0.f;
        #pragma unroll
        for (int k = 0; k < KNN; k++){
            se += emb[(size_t)selE[k]*Dd + tid];
            sr += emb[(size_t)selR[k]*Dd + tid];
        }
        store_hl1(g_avgh, g_avgl, (size_t)blk*DM + tid,      sr * 0.1f);
        store_hl1(g_avgh, g_avgl, (size_t)blk*DM + Dd + tid, se * 0.1f);
    }
}

// ---------------- tensor-core GEMM (pre-split bf16 hi/lo, STATIC smem) ------
// R12-proven skeleton: BM=128, BN=128, BK=32, static __shared__, synchronous
// staging (plain uint4 copies — no conversion), 8 warps (4m x 2n),
// warp tile 32x64, 3 mma passes (hi*hi + hi*lo + lo*hi).
// epi: 0 = relu -> g_h1 h/l, 1 = plain -> g_ffn fp32, 2 = GCN tanh+scatter,
//      3 = fused LSTM cell.

__device__ __forceinline__ void mma_bf16(float* d, const unsigned* a, unsigned b0, unsigned b1){
    asm volatile("mma.sync.aligned.m16n8k16.row.col.f32.bf16.bf16.f32 "
                 "{%0,%1,%2,%3}, {%4,%5,%6,%7}, {%8,%9}, {%0,%1,%2,%3};"
                 : "+f"(d[0]), "+f"(d[1]), "+f"(d[2]), "+f"(d[3])
                 : "r"(a[0]), "r"(a[1]), "r"(a[2]), "r"(a[3]), "r"(b0), "r"(b1));
}
__device__ __forceinline__ void ldsm4(unsigned* r, unsigned addr){
    asm volatile("ldmatrix.sync.aligned.m8n8.x4.shared.b16 {%0,%1,%2,%3}, [%4];"
                 : "=r"(r[0]), "=r"(r[1]), "=r"(r[2]), "=r"(r[3]) : "r"(addr));
}

#define TSTRIDE 40   // bf16 elems per smem row (32 + 8 pad), 80 bytes (R12-proven)

__global__ __launch_bounds__(256) void k_gemm(int mode, int hsel,
                                              const float* __restrict__ biasA,
                                              const float* __restrict__ biasB)
{
    const __nv_bfloat16 *Ah, *Al, *Wh, *Wl;
    const float* bias = biasA; const float* add = nullptr;
    __nv_bfloat16 *houth = nullptr, *houtl = nullptr;
    int K, epi, hasAdd = 0, storeBase = 0, cpZero = 0;
    switch (mode){
      case 0: Ah=g_nbh;  Al=g_nbl;  Wh=w_se1h; Wl=w_se1l; K=DM; epi=0; break;
      case 1: Ah=g_h1h;  Al=g_h1l;  Wh=w_se2h; Wl=w_se2l; K=DI; epi=1; break;
      case 4: Ah=g_ench; Al=g_encl; Wh=w_ihh;  Wl=w_ihl;  K=DM; epi=3;
              bias=g_bsum; storeBase=1; cpZero=1;
              houth=g_hah; houtl=g_hal; break;
      case 5: if (hsel){ Ah=g_hbh; Al=g_hbl; houth=g_hah; houtl=g_hal; }
              else     { Ah=g_hah; Al=g_hal; houth=g_hbh; houtl=g_hbl; }
              Wh=w_hhh; Wl=w_hhl; K=DM; epi=3;
              bias=g_sgpart; add=g_base; hasAdd=1; break;
      default:Ah=g_avgh; Al=g_avgl; Wh=w_gcnh; Wl=w_gcnl; K=DM; epi=2; break;
    }

    __shared__ __align__(16) unsigned short As_hi[128*TSTRIDE];
    __shared__ __align__(16) unsigned short As_lo[128*TSTRIDE];
    __shared__ __align__(16) unsigned short Bs_hi[128*TSTRIDE];
    __shared__ __align__(16) unsigned short Bs_lo[128*TSTRIDE];

    unsigned uAhi = (unsigned)__cvta_generic_to_shared(As_hi);
    unsigned uAlo = (unsigned)__cvta_generic_to_shared(As_lo);
    unsigned uBhi = (unsigned)__cvta_generic_to_shared(Bs_hi);
    unsigned uBlo = (unsigned)__cvta_generic_to_shared(Bs_lo);

    int tid  = threadIdx.x;
    int lane = tid & 31;
    int wid  = tid >> 5;
    int wm   = wid & 3;
    int wn   = wid >> 2;
    int m0   = blockIdx.y * 128, n0 = blockIdx.x * 128;

    int srow = tid >> 1;            // 0..127
    int skk  = (tid & 1) * 16;      // 0 or 16 (elements)

    float acc[2][8][4];
    #pragma unroll
    for (int mt = 0; mt < 2; mt++)
        #pragma unroll
        for (int nt = 0; nt < 8; nt++)
            #pragma unroll
            for (int j = 0; j < 4; j++) acc[mt][nt][j] = 0.f;

    int aRow = wm*32 + (lane & 15);
    int aKof = (lane >> 4) << 3;
    int bRow = wn*64 + (lane & 7) + ((lane >> 4) << 3);
    int bKof = ((lane >> 3) & 1) << 3;

    for (int k0 = 0; k0 < K; k0 += 32){
        // ---- stage: plain uint4 copies (pre-split, no conversion) ----
        {
            size_t gi = (size_t)(m0+srow)*K + k0 + skk;
            size_t gw = (size_t)(n0+srow)*K + k0 + skk;
            int so = srow*TSTRIDE + skk;
            *(uint4*)&As_hi[so]     = *(const uint4*)&Ah[gi];
            *(uint4*)&As_hi[so + 8] = *(const uint4*)&Ah[gi + 8];
            *(uint4*)&As_lo[so]     = *(const uint4*)&Al[gi];
            *(uint4*)&As_lo[so + 8] = *(const uint4*)&Al[gi + 8];
            *(uint4*)&Bs_hi[so]     = *(const uint4*)&Wh[gw];
            *(uint4*)&Bs_hi[so + 8] = *(const uint4*)&Wh[gw + 8];
            *(uint4*)&Bs_lo[so]     = *(const uint4*)&Wl[gw];
            *(uint4*)&Bs_lo[so + 8] = *(const uint4*)&Wl[gw + 8];
        }
        __syncthreads();

        // ---- compute: two k16 steps (R12-proven index math) ----
        #pragma unroll
        for (int ks = 0; ks < 2; ks++){
            unsigned ah[2][4], al[2][4], bh[4][4], bl[4][4];
            #pragma unroll
            for (int mt = 0; mt < 2; mt++){
                unsigned off = (unsigned)(((aRow + mt*16)*TSTRIDE + ks*16 + aKof) * 2);
                ldsm4(ah[mt], uAhi + off);
                ldsm4(al[mt], uAlo + off);
            }
            #pragma unroll
            for (int bp = 0; bp < 4; bp++){
                unsigned off = (unsigned)(((bRow + bp*16)*TSTRIDE + ks*16 + bKof) * 2);
                ldsm4(bh[bp], uBhi + off);
                ldsm4(bl[bp], uBlo + off);
            }
            #pragma unroll
            for (int mt = 0; mt < 2; mt++)
                #pragma unroll
                for (int nt = 0; nt < 8; nt++){
                    unsigned b0h = bh[nt>>1][(nt&1)*2], b1h = bh[nt>>1][(nt&1)*2+1];
                    unsigned b0l = bl[nt>>1][(nt&1)*2], b1l = bl[nt>>1][(nt&1)*2+1];
                    mma_bf16(acc[mt][nt], ah[mt], b0h, b1h);
                    mma_bf16(acc[mt][nt], ah[mt], b0l, b1l);
                    mma_bf16(acc[mt][nt], al[mt], b0h, b1h);
                }
        }
        __syncthreads();
    }

    int grp = lane >> 2, tig = lane & 3;

    if (epi == 0){
        // FFN1: relu -> g_h1 hi/lo bf16
        #pragma unroll
        for (int mt = 0; mt < 2; mt++){
            #pragma unroll
            for (int nt = 0; nt < 8; nt++){
                int n = n0 + wn*64 + nt*8 + tig*2;
                float2 bv = *(const float2*)&bias[n];
                int m = m0 + wm*32 + mt*16 + grp;
                float o0 = fmaxf(acc[mt][nt][0] + bv.x, 0.f);
                float o1 = fmaxf(acc[mt][nt][1] + bv.y, 0.f);
                float o2 = fmaxf(acc[mt][nt][2] + bv.x, 0.f);
                float o3 = fmaxf(acc[mt][nt][3] + bv.y, 0.f);
                store_hl2(g_h1h, g_h1l, (size_t)m*DI + n,     o0, o1);
                store_hl2(g_h1h, g_h1l, (size_t)(m+8)*DI + n, o2, o3);
            }
        }
    } else if (epi == 1){
        // FFN2: plain -> g_ffn fp32
        #pragma unroll
        for (int mt = 0; mt < 2; mt++){
            #pragma unroll
            for (int nt = 0; nt < 8; nt++){
                int n = n0 + wn*64 + nt*8 + tig*2;
                float2 bv = *(const float2*)&bias[n];
                int m = m0 + wm*32 + mt*16 + grp;
                *(float2*)&g_ffn[(size_t)m*DM + n] =
                    make_float2(acc[mt][nt][0] + bv.x, acc[mt][nt][1] + bv.y);
                *(float2*)&g_ffn[(size_t)(m+8)*DM + n] =
                    make_float2(acc[mt][nt][2] + bv.x, acc[mt][nt][3] + bv.y);
            }
        }
    } else if (epi == 2){
        // GCN: tanh(acc + wb + gb), scatter -> g_nb fp32 + hi/lo bf16
        #pragma unroll
        for (int mt = 0; mt < 2; mt++){
            #pragma unroll
            for (int nt = 0; nt < 8; nt++){
                int n = n0 + wn*64 + nt*8 + tig*2;   // 0..127
                float wb0 = biasA[n]   + biasB[n];
                float wb1 = biasA[n+1] + biasB[n+1];
                #pragma unroll
                for (int h2 = 0; h2 < 2; h2++){
                    int m = m0 + wm*32 + mt*16 + grp + h2*8;
                    float o0 = tanhf(acc[mt][nt][h2*2+0] + wb0);
                    float o1 = tanhf(acc[mt][nt][h2*2+1] + wb1);
                    int row, off;
                    if (m < BQ)           { row = m;                  off = 0;  }
                    else if (m < 2*BQ)    { row = m - BQ;             off = Dd; }
                    else if (m < 2*BQ+BS) { row = m - 2*BQ + BQ;      off = 0;  }
                    else                  { row = m - 2*BQ - BS + BQ; off = Dd; }
                    size_t idx = (size_t)row*DM + off + n;
                    *(float2*)&g_nb[idx] = make_float2(o0, o1);
                    store_hl2(g_nbh, g_nbl, idx, o0, o1);
                }
            }
        }
    } else {
        // fused LSTM cell (permuted gate cols: unit u at 4u..4u+3 = i,f,g,o)
        #pragma unroll
        for (int mt = 0; mt < 2; mt++){
            #pragma unroll
            for (int nt = 0; nt < 8; nt++){
                int n = n0 + wn*64 + nt*8 + tig*2;
                int m = m0 + wm*32 + mt*16 + grp;
                float2 bv = *(const float2*)&bias[n];
                float x0 = acc[mt][nt][0] + bv.x;
                float x1 = acc[mt][nt][1] + bv.y;
                float x2 = acc[mt][nt][2] + bv.x;
                float x3 = acc[mt][nt][3] + bv.y;
                if (hasAdd){
                    float2 a0 = *(const float2*)&add[(size_t)m*G4 + n];
                    float2 a1 = *(const float2*)&add[(size_t)(m+8)*G4 + n];
                    x0 += a0.x; x1 += a0.y; x2 += a1.x; x3 += a1.y;
                }
                if (storeBase){
                    *(float2*)&g_base[(size_t)m*G4 + n]     = make_float2(x0,x1);
                    *(float2*)&g_base[(size_t)(m+8)*G4 + n] = make_float2(x2,x3);
                }
                float y0 = __shfl_xor_sync(0xffffffffu, x0, 1);
                float y1 = __shfl_xor_sync(0xffffffffu, x1, 1);
                float y2 = __shfl_xor_sync(0xffffffffu, x2, 1);
                float y3 = __shfl_xor_sync(0xffffffffu, x3, 1);
                if (!(tig & 1)){
                    int u = n >> 2;
                    float cp0 = cpZero ? 0.f : g_c[(size_t)m*Hh + u];
                    float cp1 = cpZero ? 0.f : g_c[(size_t)(m+8)*Hh + u];
                    float c0 = sigm(x1)*cp0 + sigm(x0)*tanhf(y0);
                    float c1 = sigm(x3)*cp1 + sigm(x2)*tanhf(y2);
                    g_c[(size_t)m*Hh + u]     = c0;
                    g_c[(size_t)(m+8)*Hh + u] = c1;
                    if (u < DM){
                        float h0 = g_enc[(size_t)m*DM + u]     + sigm(y1)*tanhf(c0);
                        float h1 = g_enc[(size_t)(m+8)*DM + u] + sigm(y3)*tanhf(c1);
                        g_hf[(size_t)m*DM + u]     = h0;
                        g_hf[(size_t)(m+8)*DM + u] = h1;
                        store_hl1(houth, houtl, (size_t)m*DM + u,     h0);
                        store_hl1(houth, houtl, (size_t)(m+8)*DM + u, h1);
                    }
                }
            }
        }
    }
}

// ---------------- residual LayerNorm over all MB rows ----------------------
__global__ void k_ln(const float* __restrict__ g, const float* __restrict__ bb)
{
    int warp = (blockIdx.x * blockDim.x + threadIdx.x) >> 5;
    int lane = threadIdx.x & 31;
    if (warp >= MB) return;

    float v[8]; float s = 0.f;
    #pragma unroll
    for (int j = 0; j < 8; j++){
        size_t idx = (size_t)warp*DM + lane + 32*j;
        v[j] = g_ffn[idx] + g_nb[idx];
        s += v[j];
    }
    #pragma unroll
    for (int off = 16; off; off >>= 1) s += __shfl_xor_sync(0xffffffffu, s, off);
    float mu = s * (1.0f/DM);
    float q = 0.f;
    #pragma unroll
    for (int j = 0; j < 8; j++){ float d = v[j]-mu; q += d*d; }
    #pragma unroll
    for (int off = 16; off; off >>= 1) q += __shfl_xor_sync(0xffffffffu, q, off);
    float inv = rsqrtf(q * (1.0f/DM) + 1e-5f);
    #pragma unroll
    for (int j = 0; j < 8; j++){
        int d = lane + 32*j;
        size_t idx = (size_t)warp*DM + d;
        float o = (v[j]-mu)*inv*g[d] + bb[d];
        g_enc[idx] = o;
        store_hl1(g_ench, g_encl, idx, o);
    }
}

// ---------------- support_g = mean of senc rows + norm ---------------------
__global__ void k_support_post()
{
    int d = threadIdx.x;   // 256
    float s = 0.f;
    for (int r = 0; r < BS; r++) s += g_enc[(size_t)(BQ + r)*DM + d];
    s *= (1.0f/BS);
    g_sg[d] = s;
    __shared__ float red[DM];
    red[d] = s*s;
    __syncthreads();
    for (int o = 128; o; o >>= 1){
        if (d < o) red[d] += red[d+o];
        __syncthreads();
    }
    if (d == 0) g_sgnorm = sqrtf(red[0]);
}

// ---------------- sgpart/bsum in PERMUTED gate layout ----------------------
__global__ void k_sgpart(const float* __restrict__ Whh,
                         const float* __restrict__ bih, const float* __restrict__ bhh)
{
    __shared__ float s[DM];
    if (threadIdx.x < DM) s[threadIdx.x] = g_sg[threadIdx.x];
    __syncthreads();
    int p = blockIdx.x * blockDim.x + threadIdx.x;
    if (p >= G4) return;
    int orig = ((p & 3) << 9) | (p >> 2);
    const float* w = Whh + (size_t)orig*Hh + DM;
    float acc = 0.f;
    #pragma unroll 8
    for (int d = 0; d < DM; d++) acc += s[d]*w[d];
    g_sgpart[p] = acc;
    g_bsum[p]   = bih[orig] + bhh[orig];
}

// ---------------- final cosine vs support_g --------------------------------
__global__ void k_final(float* __restrict__ out)
{
    int warp = (blockIdx.x * blockDim.x + threadIdx.x) >> 5;
    int lane = threadIdx.x & 31;
    if (warp >= BQ) return;
    float dot = 0.f, nn = 0.f;
    #pragma unroll
    for (int j = 0; j < 8; j++){
        int d = lane + 32*j;
        float h = g_hf[(size_t)warp*DM + d];
        dot += h * g_sg[d];
        nn  += h * h;
    }
    #pragma unroll
    for (int off = 16; off; off >>= 1){
        dot += __shfl_xor_sync(0xffffffffu, dot, off);
        nn  += __shfl_xor_sync(0xffffffffu, nn , off);
    }
    if (lane == 0)
        out[warp] = dot / (fmaxf(sqrtf(nn), 1e-12f) * fmaxf(g_sgnorm, 1e-12f));
}

// ---------------- launch --------------------------------------------------
extern "C" void kernel_launch(void* const* d_in, const int* in_sizes, int n_in,
                              void* d_out, int out_size)
{
    const int*   query   = (const int*)  d_in[0];
    const int*   support = (const int*)  d_in[1];
    const int*   qlc     = (const int*)  d_in[2];
    const int*   qrc     = (const int*)  d_in[4];
    const int*   slc     = (const int*)  d_in[6];
    const int*   src     = (const int*)  d_in[8];
    const float* emb     = (const float*)d_in[10];
    const float* gcnW    = (const float*)d_in[11];
    const float* gcnwb   = (const float*)d_in[12];
    const float* gcnb    = (const float*)d_in[13];
    const float* sew1    = (const float*)d_in[14];
    const float* seb1    = (const float*)d_in[15];
    const float* sew2    = (const float*)d_in[16];
    const float* seb2    = (const float*)d_in[17];
    const float* lng     = (const float*)d_in[18];
    const float* lnb     = (const float*)d_in[19];
    const float* Wih     = (const float*)d_in[20];
    const float* Whh     = (const float*)d_in[21];
    const float* bih     = (const float*)d_in[22];
    const float* bhh     = (const float*)d_in[23];
    float* out = (float*)d_out;

    // 0) weight splits (bf16 hi/lo, gate rows pre-permuted; dst resolved in-kernel)
    k_splitw<<<Dd/8, 256>>>(0, gcnW);
    k_splitw<<<DI/8, 256>>>(1, sew1);
    k_splitw<<<DM/8, 256>>>(2, sew2);
    k_splitw<<<G4/8, 256>>>(3, Wih);
    k_splitw<<<G4/8, 256>>>(4, Whh);

    // 1) neighbor gather + topk + average (-> g_avg hi/lo)
    k_neighbor_avg<<<MT, 256>>>(query, support, qlc, qrc, slc, src, emb);

    // 2) GCN projection GEMM, tanh+scatter -> g_nb (+hi/lo)
    k_gemm<<<dim3(1, MT/128), 256>>>(6, 0, gcnwb, gcnb);

    // 3) merged FFN + LN -> g_enc (+hi/lo)
    k_gemm<<<dim3(DI/128, MB/128), 256>>>(0, 0, seb1, nullptr);
    k_gemm<<<dim3(DM/128, MB/128), 256>>>(1, 0, seb2, nullptr);
    k_ln<<<(MB+7)/8, 256>>>(lng, lnb);

    // 4) support_g + permuted sgpart/bsum
    k_support_post<<<1, 256>>>();
    k_sgpart<<<G4/256, 256>>>(Whh, bih, bhh);

    // 5) gates GEMMs with fused cell epilogue
    k_gemm<<<dim3(G4/128, BQ/128), 256>>>(4, 0, nullptr, nullptr); // base + step0 -> ha
    k_gemm<<<dim3(G4/128, BQ/128), 256>>>(5, 0, nullptr, nullptr); // step1: ha -> hb
    k_gemm<<<dim3(G4/128, BQ/128), 256>>>(5, 1, nullptr, nullptr); // step2: hb -> ha
    k_gemm<<<dim3(G4/128, BQ/128), 256>>>(5, 0, nullptr, nullptr); // step3: ha -> hb

    // 6) cosine output
    k_final<<<BQ/8, 256>>>(out);
}

// round 17
// speedup vs baseline: 1.8756x; 1.0034x over previous
#include <cuda_runtime.h>
#include <cuda_bf16.h>
#include <math.h>

// ---------------- problem constants ----------------
#define Dd   128
#define DM   256
#define DI   512
#define Hh   512
#define KNN  10
#define NN   64
#define BQ   4096
#define BS   128
#define G4   2048   // 4*H
#define MT   (2*BQ + 2*BS)   // 8448 neighbor rows
#define MB   (BQ + BS)       // 4224 merged encoder rows

// ---------------- scratch (device globals; allocation-free) ----------------
__device__ __align__(16) __nv_bfloat16 g_avgh[MT*DM], g_avgl[MT*DM];
__device__ __align__(16) float         g_nb  [MB*DM];
__device__ __align__(16) __nv_bfloat16 g_nbh [MB*DM], g_nbl [MB*DM];
__device__ __align__(16) __nv_bfloat16 g_h1h [MB*DI], g_h1l [MB*DI];
__device__ __align__(16) float         g_ffn [MB*DM];
__device__ __align__(16) float         g_enc [MB*DM];
__device__ __align__(16) __nv_bfloat16 g_ench[MB*DM], g_encl[MB*DM];
__device__ __align__(16) float         g_sg  [DM];
__device__ __align__(16) float         g_sgpart[G4];   // permuted gate layout
__device__ __align__(16) float         g_bsum [G4];    // permuted gate layout
__device__ __align__(16) float         g_base [BQ*G4]; // permuted gate layout
__device__ __align__(16) float         g_c   [BQ*Hh];
__device__ __align__(16) __nv_bfloat16 g_hah[BQ*DM], g_hal[BQ*DM];
__device__ __align__(16) __nv_bfloat16 g_hbh[BQ*DM], g_hbl[BQ*DM];
__device__ __align__(16) float         g_hf [BQ*DM];
__device__ float g_sgnorm;

// split weights (bf16 hi/lo, gate rows pre-permuted)
__device__ __align__(16) __nv_bfloat16 w_gcnh[Dd*DM],  w_gcnl[Dd*DM];
__device__ __align__(16) __nv_bfloat16 w_se1h[DI*DM],  w_se1l[DI*DM];
__device__ __align__(16) __nv_bfloat16 w_se2h[DM*DI],  w_se2l[DM*DI];
__device__ __align__(16) __nv_bfloat16 w_ihh [G4*DM],  w_ihl [G4*DM];
__device__ __align__(16) __nv_bfloat16 w_hhh [G4*DM],  w_hhl [G4*DM];

__device__ __forceinline__ float sigm(float x){ return 1.0f/(1.0f+expf(-x)); }

__device__ __forceinline__ void store_hl2(__nv_bfloat16* dh, __nv_bfloat16* dl,
                                          size_t idx, float x, float y){
    __nv_bfloat16 hx = __float2bfloat16(x), hy = __float2bfloat16(y);
    __nv_bfloat162 hv; hv.x = hx; hv.y = hy;
    *(__nv_bfloat162*)&dh[idx] = hv;
    __nv_bfloat162 lv;
    lv.x = __float2bfloat16(x - __bfloat162float(hx));
    lv.y = __float2bfloat16(y - __bfloat162float(hy));
    *(__nv_bfloat162*)&dl[idx] = lv;
}
__device__ __forceinline__ void store_hl1(__nv_bfloat16* dh, __nv_bfloat16* dl,
                                          size_t idx, float x){
    __nv_bfloat16 hx = __float2bfloat16(x);
    dh[idx] = hx;
    dl[idx] = __float2bfloat16(x - __bfloat162float(hx));
}

// ---------------- weight split, ALL weights in ONE launch -------------------
// Destinations resolved in-kernel (host-side device-global addresses are the
// proven R13-R15 kill-switch).
// Sections (8 rows/block): gcn 16, se1 64, se2 32, ih 256, hh 256 = 624 blocks.
__global__ void k_splitw_all(const float* __restrict__ gcnW, const float* __restrict__ sew1,
                             const float* __restrict__ sew2, const float* __restrict__ Wih,
                             const float* __restrict__ Whh)
{
    int blk = blockIdx.x;
    const float* src; __nv_bfloat16 *dh, *dl; int K, srcLd, perm, rb;
    if (blk < 16)      { src=gcnW; dh=w_gcnh; dl=w_gcnl; K=DM; srcLd=DM; perm=0; rb=blk; }
    else if (blk < 80) { src=sew1; dh=w_se1h; dl=w_se1l; K=DM; srcLd=DM; perm=0; rb=blk-16; }
    else if (blk < 112){ src=sew2; dh=w_se2h; dl=w_se2l; K=DI; srcLd=DI; perm=0; rb=blk-80; }
    else if (blk < 368){ src=Wih;  dh=w_ihh;  dl=w_ihl;  K=DM; srcLd=DM; perm=1; rb=blk-112; }
    else               { src=Whh;  dh=w_hhh;  dl=w_hhl;  K=DM; srcLd=Hh; perm=1; rb=blk-368; }

    int r    = rb * 8 + (threadIdx.x >> 5);
    int lane = threadIdx.x & 31;
    int orig = perm ? (((r & 3) << 9) | (r >> 2)) : r;
    const float* s = src + (size_t)orig * srcLd;
    for (int k = lane; k < K; k += 32)
        store_hl1(dh, dl, (size_t)r*K + k, s[k]);
}

// ---------------- neighbor averaging (low-smem, warp-parallel top-k) --------
__global__ void k_neighbor_avg(const int* __restrict__ query, const int* __restrict__ support,
                               const int* __restrict__ qlc, const int* __restrict__ qrc,
                               const int* __restrict__ slc, const int* __restrict__ src,
                               const float* __restrict__ emb)
{
    __shared__ __align__(16) float cen[Dd];
    __shared__ float sims[NN];
    __shared__ int   selE[KNN], selR[KNN];

    int blk = blockIdx.x;
    const int* conn; const int* pairs; int col, b;
    if (blk < BQ)              { b = blk;           conn = qlc; pairs = query;   col = 0; }
    else if (blk < 2*BQ)       { b = blk - BQ;      conn = qrc; pairs = query;   col = 1; }
    else if (blk < 2*BQ + BS)  { b = blk - 2*BQ;    conn = slc; pairs = support; col = 0; }
    else                       { b = blk - 2*BQ-BS; conn = src; pairs = support; col = 1; }

    int tid  = threadIdx.x;
    int lane = tid & 31;
    int w    = tid >> 5;

    int id = pairs[b*2 + col];
    if (tid < Dd) cen[tid] = emb[(size_t)id*Dd + tid];
    __syncthreads();

    float cs = 0.f;
    #pragma unroll
    for (int j = 0; j < 4; j++){ float v = cen[lane + 32*j]; cs += v*v; }
    #pragma unroll
    for (int off = 16; off; off >>= 1) cs += __shfl_xor_sync(0xffffffffu, cs, off);
    float cn = fmaxf(sqrtf(cs), 1e-8f);

    // 8 warps x 8 neighbors: streaming dot/norm (no ent caching)
    for (int q = 0; q < 8; q++){
        int n   = w*8 + q;
        int eid = conn[((size_t)b*NN + n)*2 + 1];
        float dot = 0.f, sq = 0.f;
        #pragma unroll
        for (int j = 0; j < 4; j++){
            float e = emb[(size_t)eid*Dd + lane + 32*j];
            dot += e * cen[lane + 32*j];
            sq  += e * e;
        }
        #pragma unroll
        for (int off = 16; off; off >>= 1){
            dot += __shfl_xor_sync(0xffffffffu, dot, off);
            sq  += __shfl_xor_sync(0xffffffffu, sq , off);
        }
        if (lane == 0) sims[n] = dot / (cn * fmaxf(sqrtf(sq), 1e-8f));
    }
    __syncthreads();

    // warp-parallel top-10: strict '>' + lowest-index tie-break (== jax.lax.top_k set)
    if (w == 0){
        float s0 = sims[lane], s1 = sims[lane + 32];
        for (int k = 0; k < KNN; k++){
            float v = s0; int idx = lane;
            if (s1 > v){ v = s1; idx = lane + 32; }   // strict: lower index wins ties
            #pragma unroll
            for (int off = 16; off; off >>= 1){
                float ov = __shfl_down_sync(0xffffffffu, v, off);
                int   oi = __shfl_down_sync(0xffffffffu, idx, off);
                if (ov > v || (ov == v && oi < idx)){ v = ov; idx = oi; }
            }
            idx = __shfl_sync(0xffffffffu, idx, 0);
            if (lane == 0){
                selE[k] = conn[((size_t)b*NN + idx)*2 + 1];
                selR[k] = conn[((size_t)b*NN + idx)*2 + 0];
            }
            if (idx == lane)      s0 = -1e30f;
            if (idx == lane + 32) s1 = -1e30f;
        }
    }
    __syncthreads();

    if (tid < Dd){
        float se = 0.f, sr = 0.f;
        #pragma unroll
        for (int k = 0; k < KNN; k++){
            se += emb[(size_t)selE[k]*Dd + tid];
            sr += emb[(size_t)selR[k]*Dd + tid];
        }
        store_hl1(g_avgh, g_avgl, (size_t)blk*DM + tid,      sr * 0.1f);
        store_hl1(g_avgh, g_avgl, (size_t)blk*DM + Dd + tid, se * 0.1f);
    }
}

// ---------------- tensor-core GEMM (pre-split bf16 hi/lo, STATIC smem) ------
// R16-proven skeleton + register-prefetch software pipeline: next tile's 8
// uint4 loads issue right after the first barrier, overlapping the compute.
// BM=128, BN=128, BK=32, 8 warps (4m x 2n), warp tile 32x64, 3 mma passes.
// epi: 0 = relu -> g_h1 h/l, 1 = plain -> g_ffn fp32, 2 = GCN tanh+scatter,
//      3 = fused LSTM cell.

__device__ __forceinline__ void mma_bf16(float* d, const unsigned* a, unsigned b0, unsigned b1){
    asm volatile("mma.sync.aligned.m16n8k16.row.col.f32.bf16.bf16.f32 "
                 "{%0,%1,%2,%3}, {%4,%5,%6,%7}, {%8,%9}, {%0,%1,%2,%3};"
                 : "+f"(d[0]), "+f"(d[1]), "+f"(d[2]), "+f"(d[3])
                 : "r"(a[0]), "r"(a[1]), "r"(a[2]), "r"(a[3]), "r"(b0), "r"(b1));
}
__device__ __forceinline__ void ldsm4(unsigned* r, unsigned addr){
    asm volatile("ldmatrix.sync.aligned.m8n8.x4.shared.b16 {%0,%1,%2,%3}, [%4];"
                 : "=r"(r[0]), "=r"(r[1]), "=r"(r[2]), "=r"(r[3]) : "r"(addr));
}

#define TSTRIDE 40   // bf16 elems per smem row (32 + 8 pad), 80 bytes (proven)

__global__ __launch_bounds__(256) void k_gemm(int mode, int hsel,
                                              const float* __restrict__ biasA,
                                              const float* __restrict__ biasB)
{
    const __nv_bfloat16 *Ah, *Al, *Wh, *Wl;
    const float* bias = biasA; const float* add = nullptr;
    __nv_bfloat16 *houth = nullptr, *houtl = nullptr;
    int K, epi, hasAdd = 0, storeBase = 0, cpZero = 0;
    switch (mode){
      case 0: Ah=g_nbh;  Al=g_nbl;  Wh=w_se1h; Wl=w_se1l; K=DM; epi=0; break;
      case 1: Ah=g_h1h;  Al=g_h1l;  Wh=w_se2h; Wl=w_se2l; K=DI; epi=1; break;
      case 4: Ah=g_ench; Al=g_encl; Wh=w_ihh;  Wl=w_ihl;  K=DM; epi=3;
              bias=g_bsum; storeBase=1; cpZero=1;
              houth=g_hah; houtl=g_hal; break;
      case 5: if (hsel){ Ah=g_hbh; Al=g_hbl; houth=g_hah; houtl=g_hal; }
              else     { Ah=g_hah; Al=g_hal; houth=g_hbh; houtl=g_hbl; }
              Wh=w_hhh; Wl=w_hhl; K=DM; epi=3;
              bias=g_sgpart; add=g_base; hasAdd=1; break;
      default:Ah=g_avgh; Al=g_avgl; Wh=w_gcnh; Wl=w_gcnl; K=DM; epi=2; break;
    }

    __shared__ __align__(16) unsigned short As_hi[128*TSTRIDE];
    __shared__ __align__(16) unsigned short As_lo[128*TSTRIDE];
    __shared__ __align__(16) unsigned short Bs_hi[128*TSTRIDE];
    __shared__ __align__(16) unsigned short Bs_lo[128*TSTRIDE];

    unsigned uAhi = (unsigned)__cvta_generic_to_shared(As_hi);
    unsigned uAlo = (unsigned)__cvta_generic_to_shared(As_lo);
    unsigned uBhi = (unsigned)__cvta_generic_to_shared(Bs_hi);
    unsigned uBlo = (unsigned)__cvta_generic_to_shared(Bs_lo);

    int tid  = threadIdx.x;
    int lane = tid & 31;
    int wid  = tid >> 5;
    int wm   = wid & 3;
    int wn   = wid >> 2;
    int m0   = blockIdx.y * 128, n0 = blockIdx.x * 128;

    int srow = tid >> 1;            // 0..127
    int skk  = (tid & 1) * 16;      // 0 or 16 (elements)

    float acc[2][8][4];
    #pragma unroll
    for (int mt = 0; mt < 2; mt++)
        #pragma unroll
        for (int nt = 0; nt < 8; nt++)
            #pragma unroll
            for (int j = 0; j < 4; j++) acc[mt][nt][j] = 0.f;

    int aRow = wm*32 + (lane & 15);
    int aKof = (lane >> 4) << 3;
    int bRow = wn*64 + (lane & 7) + ((lane >> 4) << 3);
    int bKof = ((lane >> 3) & 1) << 3;

    // register-prefetch pipeline
    uint4 rAh0, rAh1, rAl0, rAl1, rWh0, rWh1, rWl0, rWl1;
    #define LOADREGS(k0_) do{                                    \
        size_t gi = (size_t)(m0+srow)*K + (k0_) + skk;           \
        size_t gw = (size_t)(n0+srow)*K + (k0_) + skk;           \
        rAh0 = *(const uint4*)&Ah[gi]; rAh1 = *(const uint4*)&Ah[gi + 8]; \
        rAl0 = *(const uint4*)&Al[gi]; rAl1 = *(const uint4*)&Al[gi + 8]; \
        rWh0 = *(const uint4*)&Wh[gw]; rWh1 = *(const uint4*)&Wh[gw + 8]; \
        rWl0 = *(const uint4*)&Wl[gw]; rWl1 = *(const uint4*)&Wl[gw + 8]; \
    }while(0)

    LOADREGS(0);

    for (int k0 = 0; k0 < K; k0 += 32){
        // ---- store prefetched tile to smem ----
        {
            int so = srow*TSTRIDE + skk;
            *(uint4*)&As_hi[so]     = rAh0;
            *(uint4*)&As_hi[so + 8] = rAh1;
            *(uint4*)&As_lo[so]     = rAl0;
            *(uint4*)&As_lo[so + 8] = rAl1;
            *(uint4*)&Bs_hi[so]     = rWh0;
            *(uint4*)&Bs_hi[so + 8] = rWh1;
            *(uint4*)&Bs_lo[so]     = rWl0;
            *(uint4*)&Bs_lo[so + 8] = rWl1;
        }
        __syncthreads();

        // ---- issue next tile's global loads (latency overlaps compute) ----
        if (k0 + 32 < K) LOADREGS(k0 + 32);

        // ---- compute: two k16 steps (proven index math) ----
        #pragma unroll
        for (int ks = 0; ks < 2; ks++){
            unsigned ah[2][4], al[2][4], bh[4][4], bl[4][4];
            #pragma unroll
            for (int mt = 0; mt < 2; mt++){
                unsigned off = (unsigned)(((aRow + mt*16)*TSTRIDE + ks*16 + aKof) * 2);
                ldsm4(ah[mt], uAhi + off);
                ldsm4(al[mt], uAlo + off);
            }
            #pragma unroll
            for (int bp = 0; bp < 4; bp++){
                unsigned off = (unsigned)(((bRow + bp*16)*TSTRIDE + ks*16 + bKof) * 2);
                ldsm4(bh[bp], uBhi + off);
                ldsm4(bl[bp], uBlo + off);
            }
            #pragma unroll
            for (int mt = 0; mt < 2; mt++)
                #pragma unroll
                for (int nt = 0; nt < 8; nt++){
                    unsigned b0h = bh[nt>>1][(nt&1)*2], b1h = bh[nt>>1][(nt&1)*2+1];
                    unsigned b0l = bl[nt>>1][(nt&1)*2], b1l = bl[nt>>1][(nt&1)*2+1];
                    mma_bf16(acc[mt][nt], ah[mt], b0h, b1h);
                    mma_bf16(acc[mt][nt], ah[mt], b0l, b1l);
                    mma_bf16(acc[mt][nt], al[mt], b0h, b1h);
                }
        }
        __syncthreads();
    }
    #undef LOADREGS

    int grp = lane >> 2, tig = lane & 3;

    if (epi == 0){
        // FFN1: relu -> g_h1 hi/lo bf16
        #pragma unroll
        for (int mt = 0; mt < 2; mt++){
            #pragma unroll
            for (int nt = 0; nt < 8; nt++){
                int n = n0 + wn*64 + nt*8 + tig*2;
                float2 bv = *(const float2*)&bias[n];
                int m = m0 + wm*32 + mt*16 + grp;
                float o0 = fmaxf(acc[mt][nt][0] + bv.x, 0.f);
                float o1 = fmaxf(acc[mt][nt][1] + bv.y, 0.f);
                float o2 = fmaxf(acc[mt][nt][2] + bv.x, 0.f);
                float o3 = fmaxf(acc[mt][nt][3] + bv.y, 0.f);
                store_hl2(g_h1h, g_h1l, (size_t)m*DI + n,     o0, o1);
                store_hl2(g_h1h, g_h1l, (size_t)(m+8)*DI + n, o2, o3);
            }
        }
    } else if (epi == 1){
        // FFN2: plain -> g_ffn fp32
        #pragma unroll
        for (int mt = 0; mt < 2; mt++){
            #pragma unroll
            for (int nt = 0; nt < 8; nt++){
                int n = n0 + wn*64 + nt*8 + tig*2;
                float2 bv = *(const float2*)&bias[n];
                int m = m0 + wm*32 + mt*16 + grp;
                *(float2*)&g_ffn[(size_t)m*DM + n] =
                    make_float2(acc[mt][nt][0] + bv.x, acc[mt][nt][1] + bv.y);
                *(float2*)&g_ffn[(size_t)(m+8)*DM + n] =
                    make_float2(acc[mt][nt][2] + bv.x, acc[mt][nt][3] + bv.y);
            }
        }
    } else if (epi == 2){
        // GCN: tanh(acc + wb + gb), scatter -> g_nb fp32 + hi/lo bf16
        #pragma unroll
        for (int mt = 0; mt < 2; mt++){
            #pragma unroll
            for (int nt = 0; nt < 8; nt++){
                int n = n0 + wn*64 + nt*8 + tig*2;   // 0..127
                float wb0 = biasA[n]   + biasB[n];
                float wb1 = biasA[n+1] + biasB[n+1];
                #pragma unroll
                for (int h2 = 0; h2 < 2; h2++){
                    int m = m0 + wm*32 + mt*16 + grp + h2*8;
                    float o0 = tanhf(acc[mt][nt][h2*2+0] + wb0);
                    float o1 = tanhf(acc[mt][nt][h2*2+1] + wb1);
                    int row, off;
                    if (m < BQ)           { row = m;                  off = 0;  }
                    else if (m < 2*BQ)    { row = m - BQ;             off = Dd; }
                    else if (m < 2*BQ+BS) { row = m - 2*BQ + BQ;      off = 0;  }
                    else                  { row = m - 2*BQ - BS + BQ; off = Dd; }
                    size_t idx = (size_t)row*DM + off + n;
                    *(float2*)&g_nb[idx] = make_float2(o0, o1);
                    store_hl2(g_nbh, g_nbl, idx, o0, o1);
                }
            }
        }
    } else {
        // fused LSTM cell (permuted gate cols: unit u at 4u..4u+3 = i,f,g,o)
        #pragma unroll
        for (int mt = 0; mt < 2; mt++){
            #pragma unroll
            for (int nt = 0; nt < 8; nt++){
                int n = n0 + wn*64 + nt*8 + tig*2;
                int m = m0 + wm*32 + mt*16 + grp;
                float2 bv = *(const float2*)&bias[n];
                float x0 = acc[mt][nt][0] + bv.x;
                float x1 = acc[mt][nt][1] + bv.y;
                float x2 = acc[mt][nt][2] + bv.x;
                float x3 = acc[mt][nt][3] + bv.y;
                if (hasAdd){
                    float2 a0 = *(const float2*)&add[(size_t)m*G4 + n];
                    float2 a1 = *(const float2*)&add[(size_t)(m+8)*G4 + n];
                    x0 += a0.x; x1 += a0.y; x2 += a1.x; x3 += a1.y;
                }
                if (storeBase){
                    *(float2*)&g_base[(size_t)m*G4 + n]     = make_float2(x0,x1);
                    *(float2*)&g_base[(size_t)(m+8)*G4 + n] = make_float2(x2,x3);
                }
                float y0 = __shfl_xor_sync(0xffffffffu, x0, 1);
                float y1 = __shfl_xor_sync(0xffffffffu, x1, 1);
                float y2 = __shfl_xor_sync(0xffffffffu, x2, 1);
                float y3 = __shfl_xor_sync(0xffffffffu, x3, 1);
                if (!(tig & 1)){
                    int u = n >> 2;
                    float cp0 = cpZero ? 0.f : g_c[(size_t)m*Hh + u];
                    float cp1 = cpZero ? 0.f : g_c[(size_t)(m+8)*Hh + u];
                    float c0 = sigm(x1)*cp0 + sigm(x0)*tanhf(y0);
                    float c1 = sigm(x3)*cp1 + sigm(x2)*tanhf(y2);
                    g_c[(size_t)m*Hh + u]     = c0;
                    g_c[(size_t)(m+8)*Hh + u] = c1;
                    if (u < DM){
                        float h0 = g_enc[(size_t)m*DM + u]     + sigm(y1)*tanhf(c0);
                        float h1 = g_enc[(size_t)(m+8)*DM + u] + sigm(y3)*tanhf(c1);
                        g_hf[(size_t)m*DM + u]     = h0;
                        g_hf[(size_t)(m+8)*DM + u] = h1;
                        store_hl1(houth, houtl, (size_t)m*DM + u,     h0);
                        store_hl1(houth, houtl, (size_t)(m+8)*DM + u, h1);
                    }
                }
            }
        }
    }
}

// ---------------- residual LayerNorm over all MB rows ----------------------
__global__ void k_ln(const float* __restrict__ g, const float* __restrict__ bb)
{
    int warp = (blockIdx.x * blockDim.x + threadIdx.x) >> 5;
    int lane = threadIdx.x & 31;
    if (warp >= MB) return;

    float v[8]; float s = 0.f;
    #pragma unroll
    for (int j = 0; j < 8; j++){
        size_t idx = (size_t)warp*DM + lane + 32*j;
        v[j] = g_ffn[idx] + g_nb[idx];
        s += v[j];
    }
    #pragma unroll
    for (int off = 16; off; off >>= 1) s += __shfl_xor_sync(0xffffffffu, s, off);
    float mu = s * (1.0f/DM);
    float q = 0.f;
    #pragma unroll
    for (int j = 0; j < 8; j++){ float d = v[j]-mu; q += d*d; }
    #pragma unroll
    for (int off = 16; off; off >>= 1) q += __shfl_xor_sync(0xffffffffu, q, off);
    float inv = rsqrtf(q * (1.0f/DM) + 1e-5f);
    #pragma unroll
    for (int j = 0; j < 8; j++){
        int d = lane + 32*j;
        size_t idx = (size_t)warp*DM + d;
        float o = (v[j]-mu)*inv*g[d] + bb[d];
        g_enc[idx] = o;
        store_hl1(g_ench, g_encl, idx, o);
    }
}

// ---------------- support_g = mean of senc rows + norm ---------------------
__global__ void k_support_post()
{
    int d = threadIdx.x;   // 256
    float s = 0.f;
    for (int r = 0; r < BS; r++) s += g_enc[(size_t)(BQ + r)*DM + d];
    s *= (1.0f/BS);
    g_sg[d] = s;
    __shared__ float red[DM];
    red[d] = s*s;
    __syncthreads();
    for (int o = 128; o; o >>= 1){
        if (d < o) red[d] += red[d+o];
        __syncthreads();
    }
    if (d == 0) g_sgnorm = sqrtf(red[0]);
}

// ---------------- sgpart/bsum in PERMUTED gate layout ----------------------
__global__ void k_sgpart(const float* __restrict__ Whh,
                         const float* __restrict__ bih, const float* __restrict__ bhh)
{
    __shared__ float s[DM];
    if (threadIdx.x < DM) s[threadIdx.x] = g_sg[threadIdx.x];
    __syncthreads();
    int p = blockIdx.x * blockDim.x + threadIdx.x;
    if (p >= G4) return;
    int orig = ((p & 3) << 9) | (p >> 2);
    const float* w = Whh + (size_t)orig*Hh + DM;
    float acc = 0.f;
    #pragma unroll 8
    for (int d = 0; d < DM; d++) acc += s[d]*w[d];
    g_sgpart[p] = acc;
    g_bsum[p]   = bih[orig] + bhh[orig];
}

// ---------------- final cosine vs support_g --------------------------------
__global__ void k_final(float* __restrict__ out)
{
    int warp = (blockIdx.x * blockDim.x + threadIdx.x) >> 5;
    int lane = threadIdx.x & 31;
    if (warp >= BQ) return;
    float dot = 0.f, nn = 0.f;
    #pragma unroll
    for (int j = 0; j < 8; j++){
        int d = lane + 32*j;
        float h = g_hf[(size_t)warp*DM + d];
        dot += h * g_sg[d];
        nn  += h * h;
    }
    #pragma unroll
    for (int off = 16; off; off >>= 1){
        dot += __shfl_xor_sync(0xffffffffu, dot, off);
        nn  += __shfl_xor_sync(0xffffffffu, nn , off);
    }
    if (lane == 0)
        out[warp] = dot / (fmaxf(sqrtf(nn), 1e-12f) * fmaxf(g_sgnorm, 1e-12f));
}

// ---------------- launch --------------------------------------------------
extern "C" void kernel_launch(void* const* d_in, const int* in_sizes, int n_in,
                              void* d_out, int out_size)
{
    const int*   query   = (const int*)  d_in[0];
    const int*   support = (const int*)  d_in[1];
    const int*   qlc     = (const int*)  d_in[2];
    const int*   qrc     = (const int*)  d_in[4];
    const int*   slc     = (const int*)  d_in[6];
    const int*   src     = (const int*)  d_in[8];
    const float* emb     = (const float*)d_in[10];
    const float* gcnW    = (const float*)d_in[11];
    const float* gcnwb   = (const float*)d_in[12];
    const float* gcnb    = (const float*)d_in[13];
    const float* sew1    = (const float*)d_in[14];
    const float* seb1    = (const float*)d_in[15];
    const float* sew2    = (const float*)d_in[16];
    const float* seb2    = (const float*)d_in[17];
    const float* lng     = (const float*)d_in[18];
    const float* lnb     = (const float*)d_in[19];
    const float* Wih     = (const float*)d_in[20];
    const float* Whh     = (const float*)d_in[21];
    const float* bih     = (const float*)d_in[22];
    const float* bhh     = (const float*)d_in[23];
    float* out = (float*)d_out;

    // 0) all weight splits in ONE launch (dst resolved in-kernel)
    k_splitw_all<<<624, 256>>>(gcnW, sew1, sew2, Wih, Whh);

    // 1) neighbor gather + topk + average (-> g_avg hi/lo)
    k_neighbor_avg<<<MT, 256>>>(query, support, qlc, qrc, slc, src, emb);

    // 2) GCN projection GEMM, tanh+scatter -> g_nb (+hi/lo)
    k_gemm<<<dim3(1, MT/128), 256>>>(6, 0, gcnwb, gcnb);

    // 3) merged FFN + LN -> g_enc (+hi/lo)
    k_gemm<<<dim3(DI/128, MB/128), 256>>>(0, 0, seb1, nullptr);
    k_gemm<<<dim3(DM/128, MB/128), 256>>>(1, 0, seb2, nullptr);
    k_ln<<<(MB+7)/8, 256>>>(lng, lnb);

    // 4) support_g + permuted sgpart/bsum
    k_support_post<<<1, 256>>>();
    k_sgpart<<<G4/256, 256>>>(Whh, bih, bhh);

    // 5) gates GEMMs with fused cell epilogue
    k_gemm<<<dim3(G4/128, BQ/128), 256>>>(4, 0, nullptr, nullptr); // base + step0 -> ha
    k_gemm<<<dim3(G4/128, BQ/128), 256>>>(5, 0, nullptr, nullptr); // step1: ha -> hb
    k_gemm<<<dim3(G4/128, BQ/128), 256>>>(5, 1, nullptr, nullptr); // step2: hb -> ha
    k_gemm<<<dim3(G4/128, BQ/128), 256>>>(5, 0, nullptr, nullptr); // step3: ha -> hb

    // 6) cosine output
    k_final<<<BQ/8, 256>>>(out);
}